// round 1
// baseline (speedup 1.0000x reference)
#include <cuda_runtime.h>
#include <cstdint>

#define BB   16
#define TT   1024
#define BTN  (BB*TT)      // 16384
#define HH   256
#define WW   128
#define LL   2
#define CC   50
#define FEAT 768

// ---------------- static scratch (no cudaMalloc allowed) ----------------
__device__ float g_h0[(size_t)BTN*HH];
__device__ float g_h1[(size_t)BTN*HH];
__device__ float g_xcol[(size_t)BTN*FEAT];
__device__ float g_t1[(size_t)BTN*WW];
__device__ float g_t2[(size_t)BTN*WW];
__device__ float g_t3[(size_t)BTN*HH];
__device__ float g_pn[(size_t)BTN*WW];
__device__ float g_pc[(size_t)BTN*WW];
__device__ float g_gram[(size_t)BB*TT*TT];
__device__ float g_xx[BTN];
__device__ int   g_idx[BTN*3];
__device__ float g_s2[(size_t)BTN*3*WW];
__device__ float g_s3[(size_t)BTN*3*HH];

// ---------------- SGEMM: C[M,N] = act(A[M,K] * B[N,K]^T + bias) ----------------
// 128x128 tile, Ktile=8, 256 threads, 8x8 per-thread, double-buffered smem.
template<bool RELU, bool HASBIAS>
__global__ void __launch_bounds__(256, 2)
sgemm_nt(const float* __restrict__ A, long sA, int lda,
         const float* __restrict__ B, long sB, int ldb,
         const float* __restrict__ bias, int sBias,
         float* __restrict__ C, long sC, int ldc,
         int M, int N, int K)
{
    A += (long)blockIdx.z * sA;
    B += (long)blockIdx.z * sB;
    C += (long)blockIdx.z * sC;
    const float* bptr = bias;
    if (HASBIAS) bptr += (long)blockIdx.z * sBias;

    const int bm = blockIdx.y * 128;
    const int bn = blockIdx.x * 128;

    __shared__ __align__(16) float As[2][8][128];
    __shared__ __align__(16) float Bs[2][8][128];

    const int tid = threadIdx.x;
    const int lr  = tid >> 1;          // 0..127 (row within tile for loading)
    const int lk  = (tid & 1) << 2;    // 0 or 4 (k offset)
    const int tx  = tid & 15;          // 0..15 (n micro)
    const int ty  = tid >> 4;          // 0..15 (m micro)

    float acc[8][8];
#pragma unroll
    for (int i = 0; i < 8; i++)
#pragma unroll
        for (int j = 0; j < 8; j++) acc[i][j] = 0.f;

    const int am  = bm + lr;
    const int bnr = bn + lr;
    const bool aok = am < M;
    const bool bok = bnr < N;
    const float* Ap = A + (long)am  * lda + lk;
    const float* Bp = B + (long)bnr * ldb + lk;

    const float4 fz = make_float4(0.f, 0.f, 0.f, 0.f);
    float4 ra = aok ? *(const float4*)Ap : fz;
    float4 rb = bok ? *(const float4*)Bp : fz;
    As[0][lk+0][lr] = ra.x; As[0][lk+1][lr] = ra.y; As[0][lk+2][lr] = ra.z; As[0][lk+3][lr] = ra.w;
    Bs[0][lk+0][lr] = rb.x; Bs[0][lk+1][lr] = rb.y; Bs[0][lk+2][lr] = rb.z; Bs[0][lk+3][lr] = rb.w;
    __syncthreads();

    const int nkt = K >> 3;
    for (int kt = 0; kt < nkt; kt++) {
        const int cur = kt & 1;
        if (kt + 1 < nkt) {
            ra = aok ? *(const float4*)(Ap + (kt + 1) * 8) : fz;
            rb = bok ? *(const float4*)(Bp + (kt + 1) * 8) : fz;
        }
#pragma unroll
        for (int kk = 0; kk < 8; kk++) {
            float a[8], b[8];
            *(float4*)&a[0] = *(const float4*)&As[cur][kk][ty * 8];
            *(float4*)&a[4] = *(const float4*)&As[cur][kk][ty * 8 + 4];
            *(float4*)&b[0] = *(const float4*)&Bs[cur][kk][tx * 8];
            *(float4*)&b[4] = *(const float4*)&Bs[cur][kk][tx * 8 + 4];
#pragma unroll
            for (int i = 0; i < 8; i++)
#pragma unroll
                for (int j = 0; j < 8; j++)
                    acc[i][j] = fmaf(a[i], b[j], acc[i][j]);
        }
        if (kt + 1 < nkt) {
            const int nxt = cur ^ 1;
            As[nxt][lk+0][lr] = ra.x; As[nxt][lk+1][lr] = ra.y; As[nxt][lk+2][lr] = ra.z; As[nxt][lk+3][lr] = ra.w;
            Bs[nxt][lk+0][lr] = rb.x; Bs[nxt][lk+1][lr] = rb.y; Bs[nxt][lk+2][lr] = rb.z; Bs[nxt][lk+3][lr] = rb.w;
        }
        __syncthreads();
    }

#pragma unroll
    for (int i = 0; i < 8; i++) {
        const int m = bm + ty * 8 + i;
        if (m >= M) continue;
        float* Crow = C + (long)m * ldc;
#pragma unroll
        for (int j = 0; j < 8; j++) {
            const int n = bn + tx * 8 + j;
            if (n >= N) continue;
            float v = acc[i][j];
            if (HASBIAS) v += bptr[n];
            if (RELU) v = fmaxf(v, 0.f);
            Crow[n] = v;
        }
    }
}

// ---------------- im2col for backbone grouped conv (groups=4, k=3, pad=1) ----
// xcol[bt][g*192 + i*3 + dt] = h[b, t+dt-1, g*64+i]   (zero pad)
__global__ void im2col_k3(const float* __restrict__ h, float* __restrict__ xcol)
{
    size_t o = (size_t)blockIdx.x * blockDim.x + threadIdx.x;
    if (o >= (size_t)BTN * FEAT) return;
    int j = (int)(o % FEAT);
    size_t bt = o / FEAT;
    int t = (int)(bt & 1023);
    size_t b = bt >> 10;
    int g = j / 192, r = j % 192, i = r / 3, dt = r % 3;
    int ts = t + dt - 1;
    float v = 0.f;
    if (ts >= 0 && ts < TT) v = h[((b << 10) + ts) * HH + g * 64 + i];
    xcol[o] = v;
}

// ---------------- t2: grouped conv1d (groups=32, 4 in-ch/group, k=3, pad=1), relu
__global__ void t2conv(const float* __restrict__ x, const float* __restrict__ w,
                       const float* __restrict__ bias, float* __restrict__ y)
{
    __shared__ float sh[34][WW];
    const int b  = blockIdx.y;
    const int t0 = blockIdx.x * 32;
    const int o  = threadIdx.x;

#pragma unroll 2
    for (int r = 0; r < 34; r++) {
        int ts = t0 - 1 + r;
        sh[r][o] = (ts >= 0 && ts < TT) ? x[(((size_t)b << 10) + ts) * WW + o] : 0.f;
    }
    __syncthreads();

    float wr[12];
#pragma unroll
    for (int q = 0; q < 12; q++) wr[q] = w[o * 12 + q];
    const float bb = bias[o];
    const int g4 = (o >> 2) << 2;

    for (int tt = 0; tt < 32; tt++) {
        float acc = bb;
#pragma unroll
        for (int i = 0; i < 4; i++)
#pragma unroll
            for (int dt = 0; dt < 3; dt++)
                acc = fmaf(wr[i * 3 + dt], sh[tt + dt][g4 + i], acc);
        y[(((size_t)b << 10) + t0 + tt) * WW + o] = fmaxf(acc, 0.f);
    }
}

// ---------------- per-frame squared L2 norms (X: [BTN,256]) ----------------
__global__ void rownorm(const float* __restrict__ X, float* __restrict__ xx)
{
    int row = blockIdx.x * 8 + (threadIdx.x >> 5);
    int lane = threadIdx.x & 31;
    const float* p = X + (size_t)row * HH;
    float s = 0.f;
#pragma unroll
    for (int c = lane; c < HH; c += 32) { float v = p[c]; s = fmaf(v, v, s); }
#pragma unroll
    for (int off = 16; off; off >>= 1) s += __shfl_down_sync(0xffffffffu, s, off);
    if (!lane) xx[row] = s;
}

// ---------------- top-3 of (2*G[t,s] - xx[s]) per row; ties -> lower index ----
#define T3_INS(V, I)                                                            \
    do {                                                                        \
        float _v = (V); int _i = (I);                                           \
        if (_v > v0 || (_v == v0 && _i < i0)) {                                 \
            v2 = v1; i2 = i1; v1 = v0; i1 = i0; v0 = _v; i0 = _i;               \
        } else if (_v > v1 || (_v == v1 && _i < i1)) {                          \
            v2 = v1; i2 = i1; v1 = _v; i1 = _i;                                 \
        } else if (_v > v2 || (_v == v2 && _i < i2)) {                          \
            v2 = _v; i2 = _i;                                                   \
        }                                                                       \
    } while (0)

__global__ void top3_kernel(const float* __restrict__ gram,
                            const float* __restrict__ xx, int* __restrict__ idx)
{
    int gw = (blockIdx.x * blockDim.x + threadIdx.x) >> 5;
    if (gw >= BTN) return;
    int lane = threadIdx.x & 31;
    int b = gw >> 10, t = gw & 1023;
    const float* grow = gram + ((size_t)b * TT + t) * TT;
    const float* xr = xx + (b << 10);

    float v0 = -3e38f, v1 = -3e38f, v2 = -3e38f;
    int i0 = 1 << 29, i1 = 1 << 29, i2 = 1 << 29;
    for (int s = lane; s < TT; s += 32) {
        float v = fmaf(2.f, grow[s], -xr[s]);
        T3_INS(v, s);
    }
#pragma unroll
    for (int off = 16; off; off >>= 1) {
        float w0 = __shfl_down_sync(0xffffffffu, v0, off);
        float w1 = __shfl_down_sync(0xffffffffu, v1, off);
        float w2 = __shfl_down_sync(0xffffffffu, v2, off);
        int   j0 = __shfl_down_sync(0xffffffffu, i0, off);
        int   j1 = __shfl_down_sync(0xffffffffu, i1, off);
        int   j2 = __shfl_down_sync(0xffffffffu, i2, off);
        T3_INS(w0, j0); T3_INS(w1, j1); T3_INS(w2, j2);
    }
    if (!lane) { idx[gw * 3 + 0] = i0; idx[gw * 3 + 1] = i1; idx[gw * 3 + 2] = i2; }
}

// ---------------- fused s1-epilogue (gather + relu) + grouped s2 (4->4) ------
__global__ void s1s2(const float* __restrict__ Pn, const float* __restrict__ Pc,
                     const int* __restrict__ idx, const float* __restrict__ s2w,
                     const float* __restrict__ s2b, float* __restrict__ out)
{
    const int bt = blockIdx.x;
    const int c  = threadIdx.x;
    const int b  = bt >> 10;
    __shared__ float sh[3][WW];
    __shared__ int sidx[3];
    if (c < 3) sidx[c] = idx[bt * 3 + c];
    __syncthreads();

    const float pc = Pc[(size_t)bt * WW + c];
#pragma unroll
    for (int k = 0; k < 3; k++) {
        size_t j = ((size_t)(b << 10) + sidx[k]);
        sh[k][c] = fmaxf(Pn[j * WW + c] + pc, 0.f);
    }
    __syncthreads();

    const float w0 = s2w[c * 4 + 0], w1 = s2w[c * 4 + 1];
    const float w2 = s2w[c * 4 + 2], w3 = s2w[c * 4 + 3];
    const float bb = s2b[c];
    const int gb = (c >> 2) << 2;
#pragma unroll
    for (int k = 0; k < 3; k++) {
        float acc = bb;
        acc = fmaf(w0, sh[k][gb + 0], acc);
        acc = fmaf(w1, sh[k][gb + 1], acc);
        acc = fmaf(w2, sh[k][gb + 2], acc);
        acc = fmaf(w3, sh[k][gb + 3], acc);
        out[((size_t)bt * 3 + k) * WW + c] = fmaxf(acc, 0.f);
    }
}

// ---------------- combine: Y = relu(t3 + X + max_k s3 + s3b) -----------------
__global__ void combine(const float* __restrict__ t3, const float* __restrict__ X,
                        const float* __restrict__ s3, const float* __restrict__ s3b,
                        float* __restrict__ Y)
{
    size_t o = (size_t)blockIdx.x * HH + threadIdx.x;
    int c = threadIdx.x;
    size_t bt = blockIdx.x;
    const float* sp = s3 + bt * 3 * HH + c;
    float m = fmaxf(fmaxf(sp[0], sp[HH]), sp[2 * HH]);
    float v = t3[o] + X[o] + m + s3b[c];
    Y[o] = fmaxf(v, 0.f);
}

// ---------------- host side ----------------
static void gemm(const float* A, long sA, int lda,
                 const float* B, long sB, int ldb,
                 const float* bias, int sBias,
                 float* C, long sC, int ldc,
                 int M, int N, int K, int batches, bool relu)
{
    dim3 grid((N + 127) / 128, (M + 127) / 128, batches);
    if (relu) {
        if (bias) sgemm_nt<true,  true ><<<grid, 256>>>(A, sA, lda, B, sB, ldb, bias, sBias, C, sC, ldc, M, N, K);
        else      sgemm_nt<true,  false><<<grid, 256>>>(A, sA, lda, B, sB, ldb, bias, sBias, C, sC, ldc, M, N, K);
    } else {
        if (bias) sgemm_nt<false, true ><<<grid, 256>>>(A, sA, lda, B, sB, ldb, bias, sBias, C, sC, ldc, M, N, K);
        else      sgemm_nt<false, false><<<grid, 256>>>(A, sA, lda, B, sB, ldb, bias, sBias, C, sC, ldc, M, N, K);
    }
}

extern "C" void kernel_launch(void* const* d_in, const int* in_sizes, int n_in,
                              void* d_out, int out_size)
{
    const float* x      = (const float*)d_in[0];
    const float* fcin_w = (const float*)d_in[1];
    const float* fcin_b = (const float*)d_in[2];
    const float* conv_w = (const float*)d_in[3];
    const float* conv_b = (const float*)d_in[4];
    const float* t1w    = (const float*)d_in[5];
    const float* t1b    = (const float*)d_in[6];
    const float* t2w    = (const float*)d_in[7];
    const float* t2b    = (const float*)d_in[8];
    const float* t3w    = (const float*)d_in[9];
    const float* t3b    = (const float*)d_in[10];
    const float* s1w    = (const float*)d_in[11];
    const float* s1b    = (const float*)d_in[12];
    const float* s2w    = (const float*)d_in[13];
    const float* s2b    = (const float*)d_in[14];
    const float* s3w    = (const float*)d_in[15];
    const float* s3b    = (const float*)d_in[16];
    const float* fcw    = (const float*)d_in[17];
    const float* fcb    = (const float*)d_in[18];

    void *vp;
    float *p_h0, *p_h1, *p_xcol, *p_t1, *p_t2, *p_t3, *p_pn, *p_pc, *p_gram, *p_xx, *p_s2, *p_s3;
    int *p_idx;
    cudaGetSymbolAddress(&vp, g_h0);   p_h0   = (float*)vp;
    cudaGetSymbolAddress(&vp, g_h1);   p_h1   = (float*)vp;
    cudaGetSymbolAddress(&vp, g_xcol); p_xcol = (float*)vp;
    cudaGetSymbolAddress(&vp, g_t1);   p_t1   = (float*)vp;
    cudaGetSymbolAddress(&vp, g_t2);   p_t2   = (float*)vp;
    cudaGetSymbolAddress(&vp, g_t3);   p_t3   = (float*)vp;
    cudaGetSymbolAddress(&vp, g_pn);   p_pn   = (float*)vp;
    cudaGetSymbolAddress(&vp, g_pc);   p_pc   = (float*)vp;
    cudaGetSymbolAddress(&vp, g_gram); p_gram = (float*)vp;
    cudaGetSymbolAddress(&vp, g_xx);   p_xx   = (float*)vp;
    cudaGetSymbolAddress(&vp, g_idx);  p_idx  = (int*)vp;
    cudaGetSymbolAddress(&vp, g_s2);   p_s2   = (float*)vp;
    cudaGetSymbolAddress(&vp, g_s3);   p_s3   = (float*)vp;

    // 1) fc_in + relu : [BTN,768] x [256,768]^T -> g_h0
    gemm(x, 0, FEAT, fcin_w, 0, FEAT, fcin_b, 0, p_h0, 0, HH, BTN, HH, FEAT, 1, true);

    // 2) backbone grouped conv via im2col + 4 batched GEMMs (relu) -> g_h1
    {
        size_t tot = (size_t)BTN * FEAT;
        im2col_k3<<<(unsigned)((tot + 255) / 256), 256>>>(p_h0, p_xcol);
        gemm(p_xcol, 192, FEAT, conv_w, 64 * 192, 192, conv_b, 64,
             p_h1, 64, HH, BTN, 64, 192, 4, true);
    }

    // 3) GCNeXt blocks
    for (int l = 0; l < LL; l++) {
        const float* X = (l == 0) ? p_h1 : p_h0;
        float*       Y = (l == 0) ? p_h0 : p_h1;
        const float* t1wl = t1w + (size_t)l * WW * HH;
        const float* t3wl = t3w + (size_t)l * HH * WW;
        const float* s1wl = s1w + (size_t)l * WW * (2 * HH);
        const float* s3wl = s3w + (size_t)l * HH * WW;

        // temporal branch
        gemm(X, 0, HH, t1wl, 0, HH, t1b + (size_t)l * WW, 0, p_t1, 0, WW, BTN, WW, HH, 1, true);
        t2conv<<<dim3(TT / 32, BB), WW>>>(p_t1, t2w + (size_t)l * WW * 12, t2b + (size_t)l * WW, p_t2);
        gemm(p_t2, 0, WW, t3wl, 0, WW, t3b + (size_t)l * HH, 0, p_t3, 0, HH, BTN, HH, WW, 1, false);

        // kNN graph
        rownorm<<<BTN / 8, 256>>>(X, p_xx);
        gemm(X, (long)TT * HH, HH, X, (long)TT * HH, HH, nullptr, 0,
             p_gram, (long)TT * TT, TT, TT, TT, HH, BB, false);
        top3_kernel<<<(BTN * 32 + 255) / 256, 256>>>(p_gram, p_xx, p_idx);

        // semantic branch: Pn = X*Wn^T, Pc = X*Wc^T + b1; then gather+s2
        gemm(X, 0, HH, s1wl, 0, 2 * HH, nullptr, 0, p_pn, 0, WW, BTN, WW, HH, 1, false);
        gemm(X, 0, HH, s1wl + HH, 0, 2 * HH, s1b + (size_t)l * WW, 0, p_pc, 0, WW, BTN, WW, HH, 1, false);
        s1s2<<<BTN, WW>>>(p_pn, p_pc, p_idx, s2w + (size_t)l * WW * 4, s2b + (size_t)l * WW, p_s2);

        // s3 GEMM over BTN*3 rows, then max_k + residual + relu
        gemm(p_s2, 0, WW, s3wl, 0, WW, nullptr, 0, p_s3, 0, HH, BTN * 3, HH, WW, 1, false);
        combine<<<BTN, HH>>>(p_t3, X, p_s3, s3b + (size_t)l * HH, Y);
    }

    // 4) final fc: [BTN,256] x [50,256]^T + b -> d_out
    gemm(p_h1, 0, HH, fcw, 0, HH, fcb, 0, (float*)d_out, 0, CC, BTN, CC, HH, 1, false);
}

// round 5
// speedup vs baseline: 1.8091x; 1.8091x over previous
#include <cuda_runtime.h>
#include <cstdint>

#define BB   16
#define TT   1024
#define BTN  (BB*TT)      // 16384
#define HH   256
#define WW   128
#define LL   2
#define CC   50
#define FEAT 768

// ---------------- static scratch (no cudaMalloc allowed) ----------------
__device__ float g_h0[(size_t)BTN*HH];
__device__ float g_h1[(size_t)BTN*HH];
__device__ float g_xcol[(size_t)BTN*FEAT];
__device__ float g_t1[(size_t)BTN*WW];
__device__ float g_t2[(size_t)BTN*WW];
__device__ float g_t3[(size_t)BTN*HH];
__device__ float g_pn[(size_t)BTN*WW];
__device__ float g_pc[(size_t)BTN*WW];
__device__ float g_gram[(size_t)BB*TT*TT];
__device__ float g_xx[BTN];
__device__ int   g_idx[BTN*3];
__device__ float g_s2[(size_t)BTN*3*WW];
__device__ float g_s3[(size_t)BTN*3*HH];

// ================= helpers =================
__device__ __forceinline__ uint32_t smem_u32(const void* p) {
    uint32_t a;
    asm("{ .reg .u64 t; cvta.to.shared.u64 t, %1; cvt.u32.u64 %0, t; }" : "=r"(a) : "l"(p));
    return a;
}
__device__ __forceinline__ void ldsm4(uint32_t& r0, uint32_t& r1, uint32_t& r2, uint32_t& r3,
                                      uint32_t addr) {
    asm volatile("ldmatrix.sync.aligned.m8n8.x4.shared.b16 {%0,%1,%2,%3}, [%4];"
                 : "=r"(r0), "=r"(r1), "=r"(r2), "=r"(r3) : "r"(addr));
}
__device__ __forceinline__ void mma8(float* c, uint32_t a0, uint32_t a1, uint32_t a2, uint32_t a3,
                                     uint32_t b0, uint32_t b1) {
    asm volatile("mma.sync.aligned.m16n8k8.row.col.f32.tf32.tf32.f32 "
                 "{%0,%1,%2,%3},{%4,%5,%6,%7},{%8,%9},{%0,%1,%2,%3};"
                 : "+f"(c[0]), "+f"(c[1]), "+f"(c[2]), "+f"(c[3])
                 : "r"(a0), "r"(a1), "r"(a2), "r"(a3), "r"(b0), "r"(b1));
}
__device__ __forceinline__ uint32_t cvt_tf32(float x) {
    uint32_t h;
    asm("cvt.rna.tf32.f32 %0, %1;" : "=r"(h) : "f"(x));
    return h;
}
// swizzled byte offset within a 128-row x 128B tile
__device__ __forceinline__ uint32_t swz(uint32_t row, uint32_t chunk) {
    return row * 128u + (((chunk ^ (row & 7u)) & 7u) << 4);
}

// ============ mma.sync tf32 GEMM: C = act(A[M,K]*B[N,K]^T + bias) ============
// block 128x128, K-tile 32, 256 threads (8 warps, warp tile 64x32), 2-stage smem.
// TERMS==3: 3xTF32 (hi/lo split): hi*hi + hi*lo + lo*hi.  TERMS==1: single tf32 pass.
template<int TERMS, bool RELU, bool HASBIAS>
__global__ void __launch_bounds__(256, 1)
mgemm(const float* __restrict__ A, long sA, int lda,
      const float* __restrict__ B, long sB, int ldb,
      const float* __restrict__ bias, int sBias,
      float* __restrict__ C, long sC, int ldc,
      int M, int N, int K)
{
    constexpr int SS     = (TERMS == 3) ? 65536 : 32768;
    constexpr int OFF_AH = 0;
    constexpr int OFF_AL = 16384;
    constexpr int OFF_BH = (TERMS == 3) ? 32768 : 16384;
    constexpr int OFF_BL = 49152;

    extern __shared__ __align__(1024) char smem[];
    const uint32_t sb = smem_u32(smem);
    float* sbias = (float*)(smem + 2 * SS);

    A += (long)blockIdx.z * sA;
    B += (long)blockIdx.z * sB;
    C += (long)blockIdx.z * sC;
    const int bm = blockIdx.y * 128;
    const int bn = blockIdx.x * 128;

    const int t = threadIdx.x;
    const int lane = t & 31;
    const int wid = t >> 5;
    const int warp_m = (wid & 1) * 64;
    const int warp_n = (wid >> 1) * 32;

    if (HASBIAS && t < 128) {
        const float* bp = bias + (long)blockIdx.z * sBias;
        int n = bn + t;
        sbias[t] = (n < N) ? bp[n] : 0.f;
    }

    // ---- loader assignment: 1024 16B-chunks per tile, 4 per thread ----
    int aRow[4], aCh[4], bRow[4], bCh[4];
    const float* gA[4];
    const float* gB[4];
    bool bOk[4];
#pragma unroll
    for (int i = 0; i < 4; i++) {
        int id = t + 256 * i;
        aRow[i] = id >> 3; aCh[i] = id & 7;
        bRow[i] = id >> 3; bCh[i] = id & 7;
        gA[i] = A + (long)(bm + aRow[i]) * lda + aCh[i] * 4;
        bOk[i] = (bn + bRow[i]) < N;
        gB[i] = B + (long)(bn + bRow[i]) * ldb + bCh[i] * 4;
    }

    float4 va[4], vb[4];
    const float4 fz = make_float4(0.f, 0.f, 0.f, 0.f);

#define MG_LDG(kt)                                                            \
    {                                                                         \
        _Pragma("unroll")                                                     \
        for (int i = 0; i < 4; i++) {                                         \
            va[i] = *(const float4*)(gA[i] + (kt) * 32);                      \
            vb[i] = bOk[i] ? *(const float4*)(gB[i] + (kt) * 32) : fz;        \
        }                                                                     \
    }

#define MG_STS(st)                                                            \
    {                                                                         \
        const uint32_t s0 = sb + (uint32_t)(st) * SS;                         \
        _Pragma("unroll")                                                     \
        for (int i = 0; i < 4; i++) {                                         \
            uint32_t da = s0 + OFF_AH + swz((uint32_t)aRow[i], (uint32_t)aCh[i]); \
            uint32_t h0 = cvt_tf32(va[i].x), h1 = cvt_tf32(va[i].y);          \
            uint32_t h2 = cvt_tf32(va[i].z), h3 = cvt_tf32(va[i].w);          \
            asm volatile("st.shared.v4.b32 [%0], {%1,%2,%3,%4};"              \
                :: "r"(da), "r"(h0), "r"(h1), "r"(h2), "r"(h3) : "memory");   \
            if (TERMS == 3) {                                                 \
                float l0 = va[i].x - __uint_as_float(h0);                     \
                float l1 = va[i].y - __uint_as_float(h1);                     \
                float l2 = va[i].z - __uint_as_float(h2);                     \
                float l3 = va[i].w - __uint_as_float(h3);                     \
                asm volatile("st.shared.v4.f32 [%0], {%1,%2,%3,%4};"          \
                    :: "r"(da + (OFF_AL - OFF_AH)),                           \
                       "f"(l0), "f"(l1), "f"(l2), "f"(l3) : "memory");        \
            }                                                                 \
            uint32_t db = s0 + OFF_BH + swz((uint32_t)bRow[i], (uint32_t)bCh[i]); \
            h0 = cvt_tf32(vb[i].x); h1 = cvt_tf32(vb[i].y);                   \
            h2 = cvt_tf32(vb[i].z); h3 = cvt_tf32(vb[i].w);                   \
            asm volatile("st.shared.v4.b32 [%0], {%1,%2,%3,%4};"              \
                :: "r"(db), "r"(h0), "r"(h1), "r"(h2), "r"(h3) : "memory");   \
            if (TERMS == 3) {                                                 \
                float l0 = vb[i].x - __uint_as_float(h0);                     \
                float l1 = vb[i].y - __uint_as_float(h1);                     \
                float l2 = vb[i].z - __uint_as_float(h2);                     \
                float l3 = vb[i].w - __uint_as_float(h3);                     \
                asm volatile("st.shared.v4.f32 [%0], {%1,%2,%3,%4};"          \
                    :: "r"(db + (OFF_BL - OFF_BH)),                           \
                       "f"(l0), "f"(l1), "f"(l2), "f"(l3) : "memory");        \
            }                                                                 \
        }                                                                     \
    }

    // ---- fragment addressing (per-thread constants) ----
    const uint32_t rA  = (uint32_t)(warp_m + (lane & 7) + ((lane >> 3) & 1) * 8);
    const uint32_t cbA = (uint32_t)((lane >> 4) & 1);
    const uint32_t rB  = (uint32_t)(warp_n + (lane & 7) + ((lane >> 4) & 1) * 8);
    const uint32_t cbB = (uint32_t)((lane >> 3) & 1);
    const uint32_t xA = (uint32_t)(lane & 7);

    float acc[4][4][4];
#pragma unroll
    for (int i = 0; i < 4; i++)
#pragma unroll
        for (int j = 0; j < 4; j++)
#pragma unroll
            for (int q = 0; q < 4; q++) acc[i][j][q] = 0.f;

#define MG_MMA(st)                                                            \
    {                                                                         \
        const uint32_t s0 = sb + (uint32_t)(st) * SS;                         \
        _Pragma("unroll")                                                     \
        for (int s = 0; s < 4; s++) {                                         \
            const uint32_t coA = (((2u * s + cbA) ^ xA) & 7u) << 4;           \
            const uint32_t coB = (((2u * s + cbB) ^ xA) & 7u) << 4;           \
            uint32_t a[4][4], bh[4][2];                                       \
            _Pragma("unroll")                                                 \
            for (int i = 0; i < 4; i++)                                       \
                ldsm4(a[i][0], a[i][1], a[i][2], a[i][3],                     \
                      s0 + OFF_AH + (rA + 16u * i) * 128u + coA);             \
            _Pragma("unroll")                                                 \
            for (int p = 0; p < 2; p++)                                       \
                ldsm4(bh[2*p][0], bh[2*p][1], bh[2*p+1][0], bh[2*p+1][1],     \
                      s0 + OFF_BH + (rB + 16u * p) * 128u + coB);             \
            if (TERMS == 3) {                                                 \
                uint32_t bl[4][2];                                            \
                _Pragma("unroll")                                             \
                for (int p = 0; p < 2; p++)                                   \
                    ldsm4(bl[2*p][0], bl[2*p][1], bl[2*p+1][0], bl[2*p+1][1], \
                          s0 + OFF_BL + (rB + 16u * p) * 128u + coB);         \
                _Pragma("unroll")                                             \
                for (int i = 0; i < 4; i++)                                   \
                    _Pragma("unroll")                                         \
                    for (int j = 0; j < 4; j++) {                             \
                        mma8(acc[i][j], a[i][0], a[i][1], a[i][2], a[i][3],   \
                             bh[j][0], bh[j][1]);                             \
                        mma8(acc[i][j], a[i][0], a[i][1], a[i][2], a[i][3],   \
                             bl[j][0], bl[j][1]);                             \
                    }                                                         \
                _Pragma("unroll")                                             \
                for (int i = 0; i < 4; i++)                                   \
                    ldsm4(a[i][0], a[i][1], a[i][2], a[i][3],                 \
                          s0 + OFF_AL + (rA + 16u * i) * 128u + coA);         \
                _Pragma("unroll")                                             \
                for (int i = 0; i < 4; i++)                                   \
                    _Pragma("unroll")                                         \
                    for (int j = 0; j < 4; j++)                               \
                        mma8(acc[i][j], a[i][0], a[i][1], a[i][2], a[i][3],   \
                             bh[j][0], bh[j][1]);                             \
            } else {                                                          \
                _Pragma("unroll")                                             \
                for (int i = 0; i < 4; i++)                                   \
                    _Pragma("unroll")                                         \
                    for (int j = 0; j < 4; j++)                               \
                        mma8(acc[i][j], a[i][0], a[i][1], a[i][2], a[i][3],   \
                             bh[j][0], bh[j][1]);                             \
            }                                                                 \
        }                                                                     \
    }

    // ---- main loop, 2-stage double buffer ----
    const int nkt = K >> 5;
    MG_LDG(0);
    MG_STS(0);
    __syncthreads();
    for (int kt = 0; kt < nkt; kt++) {
        const int cur = kt & 1;
        if (kt + 1 < nkt) MG_LDG(kt + 1);
        MG_MMA(cur);
        __syncthreads();
        if (kt + 1 < nkt) {
            MG_STS(cur ^ 1);
            __syncthreads();
        }
    }

    // ---- epilogue ----
    const bool ldcEven = ((ldc & 1) == 0);
    const int mrow = bm + warp_m + (lane >> 2);
#pragma unroll
    for (int i = 0; i < 4; i++) {
        const int m0 = mrow + i * 16;
        float* C0 = C + (long)m0 * ldc;
        float* C8 = C0 + (long)8 * ldc;
#pragma unroll
        for (int j = 0; j < 4; j++) {
            const int nb = warp_n + j * 8 + (lane & 3) * 2;  // within block, even
            const int nn = bn + nb;
            if (nn >= N) continue;
            float v0 = acc[i][j][0], v1 = acc[i][j][1];
            float v2 = acc[i][j][2], v3 = acc[i][j][3];
            if (HASBIAS) {
                float b0 = sbias[nb], b1 = sbias[nb + 1];
                v0 += b0; v1 += b1; v2 += b0; v3 += b1;
            }
            if (RELU) {
                v0 = fmaxf(v0, 0.f); v1 = fmaxf(v1, 0.f);
                v2 = fmaxf(v2, 0.f); v3 = fmaxf(v3, 0.f);
            }
            if (ldcEven) {
                *(float2*)(C0 + nn) = make_float2(v0, v1);
                *(float2*)(C8 + nn) = make_float2(v2, v3);
            } else {
                C0[nn] = v0; C0[nn + 1] = v1;
                C8[nn] = v2; C8[nn + 1] = v3;
            }
        }
    }
#undef MG_LDG
#undef MG_STS
#undef MG_MMA
}

// ---------------- im2col for backbone grouped conv (groups=4, k=3, pad=1) ----
__global__ void im2col_k3(const float* __restrict__ h, float* __restrict__ xcol)
{
    size_t o = (size_t)blockIdx.x * blockDim.x + threadIdx.x;
    if (o >= (size_t)BTN * FEAT) return;
    int j = (int)(o % FEAT);
    size_t bt = o / FEAT;
    int t = (int)(bt & 1023);
    size_t b = bt >> 10;
    int g = j / 192, r = j % 192, i = r / 3, dt = r % 3;
    int ts = t + dt - 1;
    float v = 0.f;
    if (ts >= 0 && ts < TT) v = h[((b << 10) + ts) * HH + g * 64 + i];
    xcol[o] = v;
}

// ---------------- t2: grouped conv1d (groups=32, 4 in/group, k=3, pad=1), relu
__global__ void t2conv(const float* __restrict__ x, const float* __restrict__ w,
                       const float* __restrict__ bias, float* __restrict__ y)
{
    __shared__ float sh[34][WW];
    const int b  = blockIdx.y;
    const int t0 = blockIdx.x * 32;
    const int o  = threadIdx.x;

#pragma unroll 2
    for (int r = 0; r < 34; r++) {
        int ts = t0 - 1 + r;
        sh[r][o] = (ts >= 0 && ts < TT) ? x[(((size_t)b << 10) + ts) * WW + o] : 0.f;
    }
    __syncthreads();

    float wr[12];
#pragma unroll
    for (int q = 0; q < 12; q++) wr[q] = w[o * 12 + q];
    const float bb = bias[o];
    const int g4 = (o >> 2) << 2;

    for (int tt = 0; tt < 32; tt++) {
        float acc = bb;
#pragma unroll
        for (int i = 0; i < 4; i++)
#pragma unroll
            for (int dt = 0; dt < 3; dt++)
                acc = fmaf(wr[i * 3 + dt], sh[tt + dt][g4 + i], acc);
        y[(((size_t)b << 10) + t0 + tt) * WW + o] = fmaxf(acc, 0.f);
    }
}

// ---------------- per-frame squared L2 norms ----------------
__global__ void rownorm(const float* __restrict__ X, float* __restrict__ xx)
{
    int row = blockIdx.x * 8 + (threadIdx.x >> 5);
    int lane = threadIdx.x & 31;
    const float* p = X + (size_t)row * HH;
    float s = 0.f;
#pragma unroll
    for (int c = lane; c < HH; c += 32) { float v = p[c]; s = fmaf(v, v, s); }
#pragma unroll
    for (int off = 16; off; off >>= 1) s += __shfl_down_sync(0xffffffffu, s, off);
    if (!lane) xx[row] = s;
}

// ---------------- top-3 of (2*G[t,s] - xx[s]) per row; ties -> lower index ----
#define T3_INS(V, I)                                                            \
    do {                                                                        \
        float _v = (V); int _i = (I);                                           \
        if (_v > v0 || (_v == v0 && _i < i0)) {                                 \
            v2 = v1; i2 = i1; v1 = v0; i1 = i0; v0 = _v; i0 = _i;               \
        } else if (_v > v1 || (_v == v1 && _i < i1)) {                          \
            v2 = v1; i2 = i1; v1 = _v; i1 = _i;                                 \
        } else if (_v > v2 || (_v == v2 && _i < i2)) {                          \
            v2 = _v; i2 = _i;                                                   \
        }                                                                       \
    } while (0)

__global__ void top3_kernel(const float* __restrict__ gram,
                            const float* __restrict__ xx, int* __restrict__ idx)
{
    int gw = (blockIdx.x * blockDim.x + threadIdx.x) >> 5;
    if (gw >= BTN) return;
    int lane = threadIdx.x & 31;
    int b = gw >> 10, t = gw & 1023;
    const float* grow = gram + ((size_t)b * TT + t) * TT;
    const float* xr = xx + (b << 10);

    float v0 = -3e38f, v1 = -3e38f, v2 = -3e38f;
    int i0 = 1 << 29, i1 = 1 << 29, i2 = 1 << 29;
    for (int s = lane; s < TT; s += 32) {
        float v = fmaf(2.f, grow[s], -xr[s]);
        T3_INS(v, s);
    }
#pragma unroll
    for (int off = 16; off; off >>= 1) {
        float w0 = __shfl_down_sync(0xffffffffu, v0, off);
        float w1 = __shfl_down_sync(0xffffffffu, v1, off);
        float w2 = __shfl_down_sync(0xffffffffu, v2, off);
        int   j0 = __shfl_down_sync(0xffffffffu, i0, off);
        int   j1 = __shfl_down_sync(0xffffffffu, i1, off);
        int   j2 = __shfl_down_sync(0xffffffffu, i2, off);
        T3_INS(w0, j0); T3_INS(w1, j1); T3_INS(w2, j2);
    }
    if (!lane) { idx[gw * 3 + 0] = i0; idx[gw * 3 + 1] = i1; idx[gw * 3 + 2] = i2; }
}

// ---------------- fused s1-epilogue (gather + relu) + grouped s2 (4->4) ------
__global__ void s1s2(const float* __restrict__ Pn, const float* __restrict__ Pc,
                     const int* __restrict__ idx, const float* __restrict__ s2w,
                     const float* __restrict__ s2b, float* __restrict__ out)
{
    const int bt = blockIdx.x;
    const int c  = threadIdx.x;
    const int b  = bt >> 10;
    __shared__ float sh[3][WW];
    __shared__ int sidx[3];
    if (c < 3) sidx[c] = idx[bt * 3 + c];
    __syncthreads();

    const float pc = Pc[(size_t)bt * WW + c];
#pragma unroll
    for (int k = 0; k < 3; k++) {
        size_t j = ((size_t)(b << 10) + sidx[k]);
        sh[k][c] = fmaxf(Pn[j * WW + c] + pc, 0.f);
    }
    __syncthreads();

    const float w0 = s2w[c * 4 + 0], w1 = s2w[c * 4 + 1];
    const float w2 = s2w[c * 4 + 2], w3 = s2w[c * 4 + 3];
    const float bb = s2b[c];
    const int gb = (c >> 2) << 2;
#pragma unroll
    for (int k = 0; k < 3; k++) {
        float acc = bb;
        acc = fmaf(w0, sh[k][gb + 0], acc);
        acc = fmaf(w1, sh[k][gb + 1], acc);
        acc = fmaf(w2, sh[k][gb + 2], acc);
        acc = fmaf(w3, sh[k][gb + 3], acc);
        out[((size_t)bt * 3 + k) * WW + c] = fmaxf(acc, 0.f);
    }
}

// ---------------- combine: Y = relu(t3 + X + max_k s3 + s3b) -----------------
__global__ void combine(const float* __restrict__ t3, const float* __restrict__ X,
                        const float* __restrict__ s3, const float* __restrict__ s3b,
                        float* __restrict__ Y)
{
    size_t o = (size_t)blockIdx.x * HH + threadIdx.x;
    int c = threadIdx.x;
    size_t bt = blockIdx.x;
    const float* sp = s3 + bt * 3 * HH + c;
    float m = fmaxf(fmaxf(sp[0], sp[HH]), sp[2 * HH]);
    float v = t3[o] + X[o] + m + s3b[c];
    Y[o] = fmaxf(v, 0.f);
}

// ---------------- host side ----------------
static const int SHM3 = 2 * 65536 + 512;
static const int SHM1 = 2 * 32768 + 512;

static void tgemm(const float* A, long sA, int lda,
                  const float* B, long sB, int ldb,
                  const float* bias, int sBias,
                  float* C, long sC, int ldc,
                  int M, int N, int K, int batches, bool relu, int terms)
{
    dim3 grid((N + 127) / 128, M / 128, batches);
    if (terms == 3) {
        if (relu) {
            static bool init = [] {
                cudaFuncSetAttribute(mgemm<3, true, true>,
                                     cudaFuncAttributeMaxDynamicSharedMemorySize, SHM3);
                return true;
            }();
            (void)init;
            mgemm<3, true, true><<<grid, 256, SHM3>>>(A, sA, lda, B, sB, ldb, bias, sBias, C, sC, ldc, M, N, K);
        } else if (bias) {
            static bool init = [] {
                cudaFuncSetAttribute(mgemm<3, false, true>,
                                     cudaFuncAttributeMaxDynamicSharedMemorySize, SHM3);
                return true;
            }();
            (void)init;
            mgemm<3, false, true><<<grid, 256, SHM3>>>(A, sA, lda, B, sB, ldb, bias, sBias, C, sC, ldc, M, N, K);
        } else {
            static bool init = [] {
                cudaFuncSetAttribute(mgemm<3, false, false>,
                                     cudaFuncAttributeMaxDynamicSharedMemorySize, SHM3);
                return true;
            }();
            (void)init;
            mgemm<3, false, false><<<grid, 256, SHM3>>>(A, sA, lda, B, sB, ldb, bias, sBias, C, sC, ldc, M, N, K);
        }
    } else {
        static bool init = [] {
            cudaFuncSetAttribute(mgemm<1, false, true>,
                                 cudaFuncAttributeMaxDynamicSharedMemorySize, SHM1);
            return true;
        }();
        (void)init;
        mgemm<1, false, true><<<grid, 256, SHM1>>>(A, sA, lda, B, sB, ldb, bias, sBias, C, sC, ldc, M, N, K);
    }
}

extern "C" void kernel_launch(void* const* d_in, const int* in_sizes, int n_in,
                              void* d_out, int out_size)
{
    const float* x      = (const float*)d_in[0];
    const float* fcin_w = (const float*)d_in[1];
    const float* fcin_b = (const float*)d_in[2];
    const float* conv_w = (const float*)d_in[3];
    const float* conv_b = (const float*)d_in[4];
    const float* t1w    = (const float*)d_in[5];
    const float* t1b    = (const float*)d_in[6];
    const float* t2w    = (const float*)d_in[7];
    const float* t2b    = (const float*)d_in[8];
    const float* t3w    = (const float*)d_in[9];
    const float* t3b    = (const float*)d_in[10];
    const float* s1w    = (const float*)d_in[11];
    const float* s1b    = (const float*)d_in[12];
    const float* s2w    = (const float*)d_in[13];
    const float* s2b    = (const float*)d_in[14];
    const float* s3w    = (const float*)d_in[15];
    const float* s3b    = (const float*)d_in[16];
    const float* fcw    = (const float*)d_in[17];
    const float* fcb    = (const float*)d_in[18];

    void *vp;
    float *p_h0, *p_h1, *p_xcol, *p_t1, *p_t2, *p_t3, *p_pn, *p_pc, *p_gram, *p_xx, *p_s2, *p_s3;
    int *p_idx;
    cudaGetSymbolAddress(&vp, g_h0);   p_h0   = (float*)vp;
    cudaGetSymbolAddress(&vp, g_h1);   p_h1   = (float*)vp;
    cudaGetSymbolAddress(&vp, g_xcol); p_xcol = (float*)vp;
    cudaGetSymbolAddress(&vp, g_t1);   p_t1   = (float*)vp;
    cudaGetSymbolAddress(&vp, g_t2);   p_t2   = (float*)vp;
    cudaGetSymbolAddress(&vp, g_t3);   p_t3   = (float*)vp;
    cudaGetSymbolAddress(&vp, g_pn);   p_pn   = (float*)vp;
    cudaGetSymbolAddress(&vp, g_pc);   p_pc   = (float*)vp;
    cudaGetSymbolAddress(&vp, g_gram); p_gram = (float*)vp;
    cudaGetSymbolAddress(&vp, g_xx);   p_xx   = (float*)vp;
    cudaGetSymbolAddress(&vp, g_idx);  p_idx  = (int*)vp;
    cudaGetSymbolAddress(&vp, g_s2);   p_s2   = (float*)vp;
    cudaGetSymbolAddress(&vp, g_s3);   p_s3   = (float*)vp;

    // 1) fc_in + relu : [BTN,768] x [256,768]^T -> g_h0
    tgemm(x, 0, FEAT, fcin_w, 0, FEAT, fcin_b, 0, p_h0, 0, HH, BTN, HH, FEAT, 1, true, 3);

    // 2) backbone grouped conv via im2col + 4 batched GEMMs (relu) -> g_h1
    {
        size_t tot = (size_t)BTN * FEAT;
        im2col_k3<<<(unsigned)((tot + 255) / 256), 256>>>(p_h0, p_xcol);
        tgemm(p_xcol, 192, FEAT, conv_w, 64 * 192, 192, conv_b, 64,
              p_h1, 64, HH, BTN, 64, 192, 4, true, 3);
    }

    // 3) GCNeXt blocks
    for (int l = 0; l < LL; l++) {
        const float* X = (l == 0) ? p_h1 : p_h0;
        float*       Y = (l == 0) ? p_h0 : p_h1;
        const float* t1wl = t1w + (size_t)l * WW * HH;
        const float* t3wl = t3w + (size_t)l * HH * WW;
        const float* s1wl = s1w + (size_t)l * WW * (2 * HH);
        const float* s3wl = s3w + (size_t)l * HH * WW;

        // temporal branch
        tgemm(X, 0, HH, t1wl, 0, HH, t1b + (size_t)l * WW, 0, p_t1, 0, WW, BTN, WW, HH, 1, true, 3);
        t2conv<<<dim3(TT / 32, BB), WW>>>(p_t1, t2w + (size_t)l * WW * 12, t2b + (size_t)l * WW, p_t2);
        tgemm(p_t2, 0, WW, t3wl, 0, WW, t3b + (size_t)l * HH, 0, p_t3, 0, HH, BTN, HH, WW, 1, false, 3);

        // kNN graph
        rownorm<<<BTN / 8, 256>>>(X, p_xx);
        tgemm(X, (long)TT * HH, HH, X, (long)TT * HH, HH, nullptr, 0,
              p_gram, (long)TT * TT, TT, TT, TT, HH, BB, false, 3);
        top3_kernel<<<(BTN * 32 + 255) / 256, 256>>>(p_gram, p_xx, p_idx);

        // semantic branch
        tgemm(X, 0, HH, s1wl, 0, 2 * HH, nullptr, 0, p_pn, 0, WW, BTN, WW, HH, 1, false, 3);
        tgemm(X, 0, HH, s1wl + HH, 0, 2 * HH, s1b + (size_t)l * WW, 0, p_pc, 0, WW, BTN, WW, HH, 1, false, 3);
        s1s2<<<BTN, WW>>>(p_pn, p_pc, p_idx, s2w + (size_t)l * WW * 4, s2b + (size_t)l * WW, p_s2);

        // s3 GEMM over BTN*3 rows, then max_k + residual + relu
        tgemm(p_s2, 0, WW, s3wl, 0, WW, nullptr, 0, p_s3, 0, HH, BTN * 3, HH, WW, 1, false, 3);
        combine<<<BTN, HH>>>(p_t3, X, p_s3, s3b + (size_t)l * HH, Y);
    }

    // 4) final fc: [BTN,256] x [50,256]^T + b -> d_out (single-pass tf32, output-only)
    tgemm(p_h1, 0, HH, fcw, 0, HH, fcb, 0, (float*)d_out, 0, CC, BTN, CC, HH, 1, false, 1);
}

// round 6
// speedup vs baseline: 1.8428x; 1.0187x over previous
#include <cuda_runtime.h>
#include <cstdint>

#define BB   16
#define TT   1024
#define BTN  (BB*TT)      // 16384
#define HH   256
#define WW   128
#define LL   2
#define CC   50
#define FEAT 768

// ---------------- static scratch (no cudaMalloc allowed) ----------------
__device__ float g_h0[(size_t)BTN*HH];
__device__ float g_h1[(size_t)BTN*HH];
__device__ float g_big[(size_t)BTN*FEAT];     // im2col, later fused t1|pn|pc [BTN,384]
__device__ float g_t2[(size_t)BTN*WW];
__device__ float g_t3[(size_t)BTN*HH];
__device__ float g_gram[(size_t)BB*TT*TT];
__device__ float g_xx[BTN];
__device__ int   g_idx[BTN*3];
__device__ float g_s2[(size_t)BTN*3*WW];
__device__ float g_s3[(size_t)BTN*3*HH];
__device__ float g_bf[384*256];
__device__ float g_bfb[384];

// ================= helpers =================
__device__ __forceinline__ uint32_t smem_u32(const void* p) {
    uint32_t a;
    asm("{ .reg .u64 t; cvta.to.shared.u64 t, %1; cvt.u32.u64 %0, t; }" : "=r"(a) : "l"(p));
    return a;
}
__device__ __forceinline__ void ldsm4(uint32_t& r0, uint32_t& r1, uint32_t& r2, uint32_t& r3,
                                      uint32_t addr) {
    asm volatile("ldmatrix.sync.aligned.m8n8.x4.shared.b16 {%0,%1,%2,%3}, [%4];"
                 : "=r"(r0), "=r"(r1), "=r"(r2), "=r"(r3) : "r"(addr));
}
__device__ __forceinline__ void mma8(float* c, uint32_t a0, uint32_t a1, uint32_t a2, uint32_t a3,
                                     uint32_t b0, uint32_t b1) {
    asm volatile("mma.sync.aligned.m16n8k8.row.col.f32.tf32.tf32.f32 "
                 "{%0,%1,%2,%3},{%4,%5,%6,%7},{%8,%9},{%0,%1,%2,%3};"
                 : "+f"(c[0]), "+f"(c[1]), "+f"(c[2]), "+f"(c[3])
                 : "r"(a0), "r"(a1), "r"(a2), "r"(a3), "r"(b0), "r"(b1));
}
__device__ __forceinline__ uint32_t cvt_tf32(float x) {
    uint32_t h;
    asm("cvt.rna.tf32.f32 %0, %1;" : "=r"(h) : "f"(x));
    return h;
}
// swizzled byte offset within a 128-row x 128B tile
__device__ __forceinline__ uint32_t swz(uint32_t row, uint32_t chunk) {
    return row * 128u + (((chunk ^ (row & 7u)) & 7u) << 4);
}

// ============ mma.sync tf32 GEMM: C = act(A[M,K]*B[N,K]^T + bias) ============
// block 128x128, K-tile 32, 256 threads (8 warps, warp tile 64x32), 2-stage smem,
// ONE __syncthreads per k-tile (STS overlaps other warps' MMA).
// TERMS==3: 3xTF32 (hi/lo split): hi*hi + hi*lo + lo*hi.  TERMS==1: single pass.
// RELU applies only to global columns n < reluN.
template<int TERMS, bool RELU, bool HASBIAS>
__global__ void __launch_bounds__(256, 1)
mgemm(const float* __restrict__ A, long sA, int lda,
      const float* __restrict__ B, long sB, int ldb,
      const float* __restrict__ bias, int sBias,
      float* __restrict__ C, long sC, int ldc,
      int M, int N, int K, int reluN)
{
    constexpr int SS     = (TERMS == 3) ? 65536 : 32768;
    constexpr int OFF_AH = 0;
    constexpr int OFF_AL = 16384;
    constexpr int OFF_BH = (TERMS == 3) ? 32768 : 16384;
    constexpr int OFF_BL = 49152;

    extern __shared__ __align__(1024) char smem[];
    const uint32_t sb = smem_u32(smem);
    float* sbias = (float*)(smem + 2 * SS);

    A += (long)blockIdx.z * sA;
    B += (long)blockIdx.z * sB;
    C += (long)blockIdx.z * sC;
    const int bm = blockIdx.y * 128;
    const int bn = blockIdx.x * 128;

    const int t = threadIdx.x;
    const int lane = t & 31;
    const int wid = t >> 5;
    const int warp_m = (wid & 1) * 64;
    const int warp_n = (wid >> 1) * 32;

    if (HASBIAS && t < 128) {
        const float* bp = bias + (long)blockIdx.z * sBias;
        int n = bn + t;
        sbias[t] = (n < N) ? bp[n] : 0.f;
    }

    // ---- loader assignment: 1024 16B-chunks per tile, 4 per thread ----
    int aRow[4], aCh[4], bRow[4], bCh[4];
    const float* gA[4];
    const float* gB[4];
    bool bOk[4];
#pragma unroll
    for (int i = 0; i < 4; i++) {
        int id = t + 256 * i;
        aRow[i] = id >> 3; aCh[i] = id & 7;
        bRow[i] = id >> 3; bCh[i] = id & 7;
        gA[i] = A + (long)(bm + aRow[i]) * lda + aCh[i] * 4;
        bOk[i] = (bn + bRow[i]) < N;
        gB[i] = B + (long)(bn + bRow[i]) * ldb + bCh[i] * 4;
    }

    float4 va[4], vb[4];
    const float4 fz = make_float4(0.f, 0.f, 0.f, 0.f);

#define MG_LDG(kt)                                                            \
    {                                                                         \
        _Pragma("unroll")                                                     \
        for (int i = 0; i < 4; i++) {                                         \
            va[i] = *(const float4*)(gA[i] + (kt) * 32);                      \
            vb[i] = bOk[i] ? *(const float4*)(gB[i] + (kt) * 32) : fz;        \
        }                                                                     \
    }

#define MG_STS(st)                                                            \
    {                                                                         \
        const uint32_t s0 = sb + (uint32_t)(st) * SS;                         \
        _Pragma("unroll")                                                     \
        for (int i = 0; i < 4; i++) {                                         \
            uint32_t da = s0 + OFF_AH + swz((uint32_t)aRow[i], (uint32_t)aCh[i]); \
            uint32_t h0 = cvt_tf32(va[i].x), h1 = cvt_tf32(va[i].y);          \
            uint32_t h2 = cvt_tf32(va[i].z), h3 = cvt_tf32(va[i].w);          \
            asm volatile("st.shared.v4.b32 [%0], {%1,%2,%3,%4};"              \
                :: "r"(da), "r"(h0), "r"(h1), "r"(h2), "r"(h3) : "memory");   \
            if (TERMS == 3) {                                                 \
                float l0 = va[i].x - __uint_as_float(h0);                     \
                float l1 = va[i].y - __uint_as_float(h1);                     \
                float l2 = va[i].z - __uint_as_float(h2);                     \
                float l3 = va[i].w - __uint_as_float(h3);                     \
                asm volatile("st.shared.v4.f32 [%0], {%1,%2,%3,%4};"          \
                    :: "r"(da + (OFF_AL - OFF_AH)),                           \
                       "f"(l0), "f"(l1), "f"(l2), "f"(l3) : "memory");        \
            }                                                                 \
            uint32_t db = s0 + OFF_BH + swz((uint32_t)bRow[i], (uint32_t)bCh[i]); \
            h0 = cvt_tf32(vb[i].x); h1 = cvt_tf32(vb[i].y);                   \
            h2 = cvt_tf32(vb[i].z); h3 = cvt_tf32(vb[i].w);                   \
            asm volatile("st.shared.v4.b32 [%0], {%1,%2,%3,%4};"              \
                :: "r"(db), "r"(h0), "r"(h1), "r"(h2), "r"(h3) : "memory");   \
            if (TERMS == 3) {                                                 \
                float l0 = vb[i].x - __uint_as_float(h0);                     \
                float l1 = vb[i].y - __uint_as_float(h1);                     \
                float l2 = vb[i].z - __uint_as_float(h2);                     \
                float l3 = vb[i].w - __uint_as_float(h3);                     \
                asm volatile("st.shared.v4.f32 [%0], {%1,%2,%3,%4};"          \
                    :: "r"(db + (OFF_BL - OFF_BH)),                           \
                       "f"(l0), "f"(l1), "f"(l2), "f"(l3) : "memory");        \
            }                                                                 \
        }                                                                     \
    }

    // ---- fragment addressing (per-thread constants) ----
    const uint32_t rA  = (uint32_t)(warp_m + (lane & 7) + ((lane >> 3) & 1) * 8);
    const uint32_t cbA = (uint32_t)((lane >> 4) & 1);
    const uint32_t rB  = (uint32_t)(warp_n + (lane & 7) + ((lane >> 4) & 1) * 8);
    const uint32_t cbB = (uint32_t)((lane >> 3) & 1);
    const uint32_t xA = (uint32_t)(lane & 7);

    float acc[4][4][4];
#pragma unroll
    for (int i = 0; i < 4; i++)
#pragma unroll
        for (int j = 0; j < 4; j++)
#pragma unroll
            for (int q = 0; q < 4; q++) acc[i][j][q] = 0.f;

#define MG_MMA(st)                                                            \
    {                                                                         \
        const uint32_t s0 = sb + (uint32_t)(st) * SS;                         \
        _Pragma("unroll")                                                     \
        for (int s = 0; s < 4; s++) {                                         \
            const uint32_t coA = (((2u * s + cbA) ^ xA) & 7u) << 4;           \
            const uint32_t coB = (((2u * s + cbB) ^ xA) & 7u) << 4;           \
            uint32_t a[4][4], bh[4][2];                                       \
            _Pragma("unroll")                                                 \
            for (int i = 0; i < 4; i++)                                       \
                ldsm4(a[i][0], a[i][1], a[i][2], a[i][3],                     \
                      s0 + OFF_AH + (rA + 16u * i) * 128u + coA);             \
            _Pragma("unroll")                                                 \
            for (int p = 0; p < 2; p++)                                       \
                ldsm4(bh[2*p][0], bh[2*p][1], bh[2*p+1][0], bh[2*p+1][1],     \
                      s0 + OFF_BH + (rB + 16u * p) * 128u + coB);             \
            if (TERMS == 3) {                                                 \
                uint32_t bl[4][2];                                            \
                _Pragma("unroll")                                             \
                for (int p = 0; p < 2; p++)                                   \
                    ldsm4(bl[2*p][0], bl[2*p][1], bl[2*p+1][0], bl[2*p+1][1], \
                          s0 + OFF_BL + (rB + 16u * p) * 128u + coB);         \
                _Pragma("unroll")                                             \
                for (int i = 0; i < 4; i++)                                   \
                    _Pragma("unroll")                                         \
                    for (int j = 0; j < 4; j++) {                             \
                        mma8(acc[i][j], a[i][0], a[i][1], a[i][2], a[i][3],   \
                             bh[j][0], bh[j][1]);                             \
                        mma8(acc[i][j], a[i][0], a[i][1], a[i][2], a[i][3],   \
                             bl[j][0], bl[j][1]);                             \
                    }                                                         \
                _Pragma("unroll")                                             \
                for (int i = 0; i < 4; i++)                                   \
                    ldsm4(a[i][0], a[i][1], a[i][2], a[i][3],                 \
                          s0 + OFF_AL + (rA + 16u * i) * 128u + coA);         \
                _Pragma("unroll")                                             \
                for (int i = 0; i < 4; i++)                                   \
                    _Pragma("unroll")                                         \
                    for (int j = 0; j < 4; j++)                               \
                        mma8(acc[i][j], a[i][0], a[i][1], a[i][2], a[i][3],   \
                             bh[j][0], bh[j][1]);                             \
            } else {                                                          \
                _Pragma("unroll")                                             \
                for (int i = 0; i < 4; i++)                                   \
                    _Pragma("unroll")                                         \
                    for (int j = 0; j < 4; j++)                               \
                        mma8(acc[i][j], a[i][0], a[i][1], a[i][2], a[i][3],   \
                             bh[j][0], bh[j][1]);                             \
            }                                                                 \
        }                                                                     \
    }

    // ---- main loop: ONE sync per k-tile ----
    const int nkt = K >> 5;
    MG_LDG(0);
    MG_STS(0);
    __syncthreads();
    for (int kt = 0; kt < nkt; kt++) {
        const int cur = kt & 1;
        const bool more = (kt + 1 < nkt);
        if (more) MG_LDG(kt + 1);
        MG_MMA(cur);
        if (more) {
            MG_STS(cur ^ 1);   // writes other stage; prior readers fenced last iter
            __syncthreads();
        }
    }

    // ---- epilogue ----
    const bool ldcEven = ((ldc & 1) == 0);
    const int mrow = bm + warp_m + (lane >> 2);
#pragma unroll
    for (int i = 0; i < 4; i++) {
        const int m0 = mrow + i * 16;
        float* C0 = C + (long)m0 * ldc;
        float* C8 = C0 + (long)8 * ldc;
#pragma unroll
        for (int j = 0; j < 4; j++) {
            const int nb = warp_n + j * 8 + (lane & 3) * 2;  // within block, even
            const int nn = bn + nb;
            if (nn >= N) continue;
            float v0 = acc[i][j][0], v1 = acc[i][j][1];
            float v2 = acc[i][j][2], v3 = acc[i][j][3];
            if (HASBIAS) {
                float b0 = sbias[nb], b1 = sbias[nb + 1];
                v0 += b0; v1 += b1; v2 += b0; v3 += b1;
            }
            if (RELU && nn < reluN) {
                v0 = fmaxf(v0, 0.f); v1 = fmaxf(v1, 0.f);
                v2 = fmaxf(v2, 0.f); v3 = fmaxf(v3, 0.f);
            }
            if (ldcEven) {
                *(float2*)(C0 + nn) = make_float2(v0, v1);
                *(float2*)(C8 + nn) = make_float2(v2, v3);
            } else {
                C0[nn] = v0; C0[nn + 1] = v1;
                C8[nn] = v2; C8[nn + 1] = v3;
            }
        }
    }
#undef MG_LDG
#undef MG_STS
#undef MG_MMA
}

// ---------------- im2col for backbone grouped conv (groups=4, k=3, pad=1) ----
__global__ void im2col_k3(const float* __restrict__ h, float* __restrict__ xcol)
{
    size_t o = (size_t)blockIdx.x * blockDim.x + threadIdx.x;
    if (o >= (size_t)BTN * FEAT) return;
    int j = (int)(o % FEAT);
    size_t bt = o / FEAT;
    int t = (int)(bt & 1023);
    size_t b = bt >> 10;
    int g = j / 192, r = j % 192, i = r / 3, dt = r % 3;
    int ts = t + dt - 1;
    float v = 0.f;
    if (ts >= 0 && ts < TT) v = h[((b << 10) + ts) * HH + g * 64 + i];
    xcol[o] = v;
}

// ---------------- pack fused B = [t1w; s1w_nbr; s1w_ctr], bias = [t1b;0;s1b] --
__global__ void pack_fused(const float* __restrict__ t1w, const float* __restrict__ t1b,
                           const float* __restrict__ s1w, const float* __restrict__ s1b,
                           float* __restrict__ Bf, float* __restrict__ bf)
{
    int i = blockIdx.x * 256 + threadIdx.x;
    if (i < 384 * 256) {
        int r = i >> 8, c = i & 255;
        float v;
        if (r < 128)      v = t1w[r * 256 + c];
        else if (r < 256) v = s1w[(r - 128) * 512 + c];
        else              v = s1w[(r - 256) * 512 + 256 + c];
        Bf[i] = v;
    }
    if (i < 384)
        bf[i] = (i < 128) ? t1b[i] : (i < 256 ? 0.f : s1b[i - 256]);
}

// ---------------- t2: grouped conv1d (groups=32, 4 in/group, k=3, pad=1), relu
__global__ void t2conv(const float* __restrict__ x, int ldx,
                       const float* __restrict__ w,
                       const float* __restrict__ bias, float* __restrict__ y)
{
    __shared__ float sh[34][WW];
    const int b  = blockIdx.y;
    const int t0 = blockIdx.x * 32;
    const int o  = threadIdx.x;

#pragma unroll 2
    for (int r = 0; r < 34; r++) {
        int ts = t0 - 1 + r;
        sh[r][o] = (ts >= 0 && ts < TT) ? x[(((size_t)b << 10) + ts) * ldx + o] : 0.f;
    }
    __syncthreads();

    float wr[12];
#pragma unroll
    for (int q = 0; q < 12; q++) wr[q] = w[o * 12 + q];
    const float bb = bias[o];
    const int g4 = (o >> 2) << 2;

    for (int tt = 0; tt < 32; tt++) {
        float acc = bb;
#pragma unroll
        for (int i = 0; i < 4; i++)
#pragma unroll
            for (int dt = 0; dt < 3; dt++)
                acc = fmaf(wr[i * 3 + dt], sh[tt + dt][g4 + i], acc);
        y[(((size_t)b << 10) + t0 + tt) * WW + o] = fmaxf(acc, 0.f);
    }
}

// ---------------- per-frame squared L2 norms ----------------
__global__ void rownorm(const float* __restrict__ X, float* __restrict__ xx)
{
    int row = blockIdx.x * 8 + (threadIdx.x >> 5);
    int lane = threadIdx.x & 31;
    const float* p = X + (size_t)row * HH;
    float s = 0.f;
#pragma unroll
    for (int c = lane; c < HH; c += 32) { float v = p[c]; s = fmaf(v, v, s); }
#pragma unroll
    for (int off = 16; off; off >>= 1) s += __shfl_down_sync(0xffffffffu, s, off);
    if (!lane) xx[row] = s;
}

// ---------------- top-3 of (2*G[t,s] - xx[s]) per row; ties -> lower index ----
#define T3_INS(V, I)                                                            \
    do {                                                                        \
        float _v = (V); int _i = (I);                                           \
        if (_v > v0 || (_v == v0 && _i < i0)) {                                 \
            v2 = v1; i2 = i1; v1 = v0; i1 = i0; v0 = _v; i0 = _i;               \
        } else if (_v > v1 || (_v == v1 && _i < i1)) {                          \
            v2 = v1; i2 = i1; v1 = _v; i1 = _i;                                 \
        } else if (_v > v2 || (_v == v2 && _i < i2)) {                          \
            v2 = _v; i2 = _i;                                                   \
        }                                                                       \
    } while (0)

__global__ void top3_kernel(const float* __restrict__ gram,
                            const float* __restrict__ xx, int* __restrict__ idx)
{
    int gw = (blockIdx.x * blockDim.x + threadIdx.x) >> 5;
    if (gw >= BTN) return;
    int lane = threadIdx.x & 31;
    int b = gw >> 10, t = gw & 1023;
    const float* grow = gram + ((size_t)b * TT + t) * TT;
    const float* xr = xx + (b << 10);

    float v0 = -3e38f, v1 = -3e38f, v2 = -3e38f;
    int i0 = 1 << 29, i1 = 1 << 29, i2 = 1 << 29;
    for (int s = lane; s < TT; s += 32) {
        float v = fmaf(2.f, grow[s], -xr[s]);
        T3_INS(v, s);
    }
#pragma unroll
    for (int off = 16; off; off >>= 1) {
        float w0 = __shfl_down_sync(0xffffffffu, v0, off);
        float w1 = __shfl_down_sync(0xffffffffu, v1, off);
        float w2 = __shfl_down_sync(0xffffffffu, v2, off);
        int   j0 = __shfl_down_sync(0xffffffffu, i0, off);
        int   j1 = __shfl_down_sync(0xffffffffu, i1, off);
        int   j2 = __shfl_down_sync(0xffffffffu, i2, off);
        T3_INS(w0, j0); T3_INS(w1, j1); T3_INS(w2, j2);
    }
    if (!lane) { idx[gw * 3 + 0] = i0; idx[gw * 3 + 1] = i1; idx[gw * 3 + 2] = i2; }
}

// ---------------- fused s1-epilogue (gather + relu) + grouped s2 (4->4) ------
__global__ void s1s2(const float* __restrict__ Pn, const float* __restrict__ Pc, int ld,
                     const int* __restrict__ idx, const float* __restrict__ s2w,
                     const float* __restrict__ s2b, float* __restrict__ out)
{
    const int bt = blockIdx.x;
    const int c  = threadIdx.x;
    const int b  = bt >> 10;
    __shared__ float sh[3][WW];
    __shared__ int sidx[3];
    if (c < 3) sidx[c] = idx[bt * 3 + c];
    __syncthreads();

    const float pc = Pc[(size_t)bt * ld + c];
#pragma unroll
    for (int k = 0; k < 3; k++) {
        size_t j = ((size_t)(b << 10) + sidx[k]);
        sh[k][c] = fmaxf(Pn[j * ld + c] + pc, 0.f);
    }
    __syncthreads();

    const float w0 = s2w[c * 4 + 0], w1 = s2w[c * 4 + 1];
    const float w2 = s2w[c * 4 + 2], w3 = s2w[c * 4 + 3];
    const float bb = s2b[c];
    const int gb = (c >> 2) << 2;
#pragma unroll
    for (int k = 0; k < 3; k++) {
        float acc = bb;
        acc = fmaf(w0, sh[k][gb + 0], acc);
        acc = fmaf(w1, sh[k][gb + 1], acc);
        acc = fmaf(w2, sh[k][gb + 2], acc);
        acc = fmaf(w3, sh[k][gb + 3], acc);
        out[((size_t)bt * 3 + k) * WW + c] = fmaxf(acc, 0.f);
    }
}

// ---------------- combine: Y = relu(t3 + X + max_k s3 + s3b) -----------------
__global__ void combine(const float* __restrict__ t3, const float* __restrict__ X,
                        const float* __restrict__ s3, const float* __restrict__ s3b,
                        float* __restrict__ Y)
{
    size_t o = (size_t)blockIdx.x * HH + threadIdx.x;
    int c = threadIdx.x;
    size_t bt = blockIdx.x;
    const float* sp = s3 + bt * 3 * HH + c;
    float m = fmaxf(fmaxf(sp[0], sp[HH]), sp[2 * HH]);
    float v = t3[o] + X[o] + m + s3b[c];
    Y[o] = fmaxf(v, 0.f);
}

// ---------------- host side ----------------
static const int SHM3 = 2 * 65536 + 512;
static const int SHM1 = 2 * 32768 + 512;

static void tgemm(const float* A, long sA, int lda,
                  const float* B, long sB, int ldb,
                  const float* bias, int sBias,
                  float* C, long sC, int ldc,
                  int M, int N, int K, int batches, bool relu, int reluN, int terms)
{
    dim3 grid((N + 127) / 128, M / 128, batches);
    if (terms == 3) {
        if (relu) {
            static bool init = [] {
                cudaFuncSetAttribute(mgemm<3, true, true>,
                                     cudaFuncAttributeMaxDynamicSharedMemorySize, SHM3);
                return true;
            }();
            (void)init;
            mgemm<3, true, true><<<grid, 256, SHM3>>>(A, sA, lda, B, sB, ldb, bias, sBias, C, sC, ldc, M, N, K, reluN);
        } else if (bias) {
            static bool init = [] {
                cudaFuncSetAttribute(mgemm<3, false, true>,
                                     cudaFuncAttributeMaxDynamicSharedMemorySize, SHM3);
                return true;
            }();
            (void)init;
            mgemm<3, false, true><<<grid, 256, SHM3>>>(A, sA, lda, B, sB, ldb, bias, sBias, C, sC, ldc, M, N, K, 0);
        } else {
            static bool init = [] {
                cudaFuncSetAttribute(mgemm<3, false, false>,
                                     cudaFuncAttributeMaxDynamicSharedMemorySize, SHM3);
                return true;
            }();
            (void)init;
            mgemm<3, false, false><<<grid, 256, SHM3>>>(A, sA, lda, B, sB, ldb, bias, sBias, C, sC, ldc, M, N, K, 0);
        }
    } else {
        static bool init = [] {
            cudaFuncSetAttribute(mgemm<1, false, true>,
                                 cudaFuncAttributeMaxDynamicSharedMemorySize, SHM1);
            return true;
        }();
        (void)init;
        mgemm<1, false, true><<<grid, 256, SHM1>>>(A, sA, lda, B, sB, ldb, bias, sBias, C, sC, ldc, M, N, K, 0);
    }
}

extern "C" void kernel_launch(void* const* d_in, const int* in_sizes, int n_in,
                              void* d_out, int out_size)
{
    const float* x      = (const float*)d_in[0];
    const float* fcin_w = (const float*)d_in[1];
    const float* fcin_b = (const float*)d_in[2];
    const float* conv_w = (const float*)d_in[3];
    const float* conv_b = (const float*)d_in[4];
    const float* t1w    = (const float*)d_in[5];
    const float* t1b    = (const float*)d_in[6];
    const float* t2w    = (const float*)d_in[7];
    const float* t2b    = (const float*)d_in[8];
    const float* t3w    = (const float*)d_in[9];
    const float* t3b    = (const float*)d_in[10];
    const float* s1w    = (const float*)d_in[11];
    const float* s1b    = (const float*)d_in[12];
    const float* s2w    = (const float*)d_in[13];
    const float* s2b    = (const float*)d_in[14];
    const float* s3w    = (const float*)d_in[15];
    const float* s3b    = (const float*)d_in[16];
    const float* fcw    = (const float*)d_in[17];
    const float* fcb    = (const float*)d_in[18];

    void *vp;
    float *p_h0, *p_h1, *p_big, *p_t2, *p_t3, *p_gram, *p_xx, *p_s2, *p_s3, *p_bf, *p_bfb;
    int *p_idx;
    cudaGetSymbolAddress(&vp, g_h0);   p_h0   = (float*)vp;
    cudaGetSymbolAddress(&vp, g_h1);   p_h1   = (float*)vp;
    cudaGetSymbolAddress(&vp, g_big);  p_big  = (float*)vp;
    cudaGetSymbolAddress(&vp, g_t2);   p_t2   = (float*)vp;
    cudaGetSymbolAddress(&vp, g_t3);   p_t3   = (float*)vp;
    cudaGetSymbolAddress(&vp, g_gram); p_gram = (float*)vp;
    cudaGetSymbolAddress(&vp, g_xx);   p_xx   = (float*)vp;
    cudaGetSymbolAddress(&vp, g_idx);  p_idx  = (int*)vp;
    cudaGetSymbolAddress(&vp, g_s2);   p_s2   = (float*)vp;
    cudaGetSymbolAddress(&vp, g_s3);   p_s3   = (float*)vp;
    cudaGetSymbolAddress(&vp, g_bf);   p_bf   = (float*)vp;
    cudaGetSymbolAddress(&vp, g_bfb);  p_bfb  = (float*)vp;

    // 1) fc_in + relu : [BTN,768] x [256,768]^T -> g_h0
    tgemm(x, 0, FEAT, fcin_w, 0, FEAT, fcin_b, 0, p_h0, 0, HH, BTN, HH, FEAT, 1, true, HH, 3);

    // 2) backbone grouped conv via im2col + 4 batched GEMMs (relu) -> g_h1
    {
        size_t tot = (size_t)BTN * FEAT;
        im2col_k3<<<(unsigned)((tot + 255) / 256), 256>>>(p_h0, p_big);
        tgemm(p_big, 192, FEAT, conv_w, 64 * 192, 192, conv_b, 64,
              p_h1, 64, HH, BTN, 64, 192, 4, true, 64, 3);
    }

    // 3) GCNeXt blocks
    for (int l = 0; l < LL; l++) {
        const float* X = (l == 0) ? p_h1 : p_h0;
        float*       Y = (l == 0) ? p_h0 : p_h1;
        const float* t1wl = t1w + (size_t)l * WW * HH;
        const float* t3wl = t3w + (size_t)l * HH * WW;
        const float* s1wl = s1w + (size_t)l * WW * (2 * HH);
        const float* s3wl = s3w + (size_t)l * HH * WW;

        // fused t1|Pn|Pc GEMM: N=384, relu only on first 128 cols (t1)
        pack_fused<<<384, 256>>>(t1wl, t1b + (size_t)l * WW, s1wl, s1b + (size_t)l * WW,
                                 p_bf, p_bfb);
        tgemm(X, 0, HH, p_bf, 0, HH, p_bfb, 0, p_big, 0, 384, BTN, 384, HH, 1, true, 128, 3);

        // temporal branch rest
        t2conv<<<dim3(TT / 32, BB), WW>>>(p_big, 384, t2w + (size_t)l * WW * 12,
                                          t2b + (size_t)l * WW, p_t2);
        tgemm(p_t2, 0, WW, t3wl, 0, WW, t3b + (size_t)l * HH, 0, p_t3, 0, HH, BTN, HH, WW, 1, false, 0, 3);

        // kNN graph
        rownorm<<<BTN / 8, 256>>>(X, p_xx);
        tgemm(X, (long)TT * HH, HH, X, (long)TT * HH, HH, nullptr, 0,
              p_gram, (long)TT * TT, TT, TT, TT, HH, BB, false, 0, 3);
        top3_kernel<<<(BTN * 32 + 255) / 256, 256>>>(p_gram, p_xx, p_idx);

        // semantic branch: gather from fused Pn/Pc columns
        s1s2<<<BTN, WW>>>(p_big + 128, p_big + 256, 384, p_idx,
                          s2w + (size_t)l * WW * 4, s2b + (size_t)l * WW, p_s2);

        // s3 GEMM over BTN*3 rows, then max_k + residual + relu
        tgemm(p_s2, 0, WW, s3wl, 0, WW, nullptr, 0, p_s3, 0, HH, BTN * 3, HH, WW, 1, false, 0, 3);
        combine<<<BTN, HH>>>(p_t3, X, p_s3, s3b + (size_t)l * HH, Y);
    }

    // 4) final fc: [BTN,256] x [50,256]^T + b -> d_out (single-pass tf32)
    tgemm(p_h1, 0, HH, fcw, 0, HH, fcb, 0, (float*)d_out, 0, CC, BTN, CC, HH, 1, false, 0, 1);
}

// round 7
// speedup vs baseline: 1.9772x; 1.0729x over previous
#include <cuda_runtime.h>
#include <cstdint>

#define BB   16
#define TT   1024
#define BTN  (BB*TT)      // 16384
#define HH   256
#define WW   128
#define LL   2
#define CC   50
#define FEAT 768

// ---------------- static scratch (no cudaMalloc allowed) ----------------
__device__ float g_h0[(size_t)BTN*HH];
__device__ float g_h1[(size_t)BTN*HH];
__device__ float g_big[(size_t)BTN*FEAT];     // im2col, later fused t1|pn|pc [BTN,384]
__device__ float g_t2[(size_t)BTN*WW];
__device__ float g_t3[(size_t)BTN*HH];
__device__ float g_gram[(size_t)BB*TT*TT];
__device__ float g_xx[BTN];
__device__ int   g_idx[BTN*3];
__device__ float g_s2[(size_t)BTN*3*WW];
__device__ float g_s3[(size_t)BTN*3*HH];
__device__ float g_bf[384*256];
__device__ float g_bfb[384];

// ================= helpers =================
__device__ __forceinline__ uint32_t smem_u32(const void* p) {
    uint32_t a;
    asm("{ .reg .u64 t; cvta.to.shared.u64 t, %1; cvt.u32.u64 %0, t; }" : "=r"(a) : "l"(p));
    return a;
}
__device__ __forceinline__ void ldsm4(uint32_t& r0, uint32_t& r1, uint32_t& r2, uint32_t& r3,
                                      uint32_t addr) {
    asm volatile("ldmatrix.sync.aligned.m8n8.x4.shared.b16 {%0,%1,%2,%3}, [%4];"
                 : "=r"(r0), "=r"(r1), "=r"(r2), "=r"(r3) : "r"(addr));
}
__device__ __forceinline__ void mma8(float* c, uint32_t a0, uint32_t a1, uint32_t a2, uint32_t a3,
                                     uint32_t b0, uint32_t b1) {
    asm volatile("mma.sync.aligned.m16n8k8.row.col.f32.tf32.tf32.f32 "
                 "{%0,%1,%2,%3},{%4,%5,%6,%7},{%8,%9},{%0,%1,%2,%3};"
                 : "+f"(c[0]), "+f"(c[1]), "+f"(c[2]), "+f"(c[3])
                 : "r"(a0), "r"(a1), "r"(a2), "r"(a3), "r"(b0), "r"(b1));
}
__device__ __forceinline__ uint32_t cvt_tf32(float x) {
    uint32_t h;
    asm("cvt.rna.tf32.f32 %0, %1;" : "=r"(h) : "f"(x));
    return h;
}
// swizzled byte offset within a 128-row x 128B tile
__device__ __forceinline__ uint32_t swz(uint32_t row, uint32_t chunk) {
    return row * 128u + (((chunk ^ (row & 7u)) & 7u) << 4);
}

#define CP16(dst, src, sz) \
    asm volatile("cp.async.cg.shared.global [%0], [%1], 16, %2;" \
                 :: "r"(dst), "l"(src), "r"(sz))
#define CPCOMMIT() asm volatile("cp.async.commit_group;" ::: "memory")
#define CPWAIT2()  asm volatile("cp.async.wait_group 2;" ::: "memory")

// ============ mma.sync tf32 GEMM: C = act(A[M,K]*B[N,K]^T + bias) ============
// block 128x128, K-tile 32, 256 threads (8 warps, warp tile 64x32).
// cp.async 4-stage pipeline, raw fp32 in smem, tf32 hi/lo split in registers.
// TERMS==3: 3xTF32 (hi*hi + hi*lo + lo*hi).  TERMS==1: single tf32 pass.
// RELU applies only to global columns n < reluN.
// GRAMSYM: A==B symmetric output; compute upper tiles only, mirror via smem.
template<int TERMS, bool RELU, bool HASBIAS, bool GRAMSYM>
__global__ void __launch_bounds__(256, 1)
mgemm(const float* __restrict__ A, long sA, int lda,
      const float* __restrict__ B, long sB, int ldb,
      const float* __restrict__ bias, int sBias,
      float* __restrict__ C, long sC, int ldc,
      int M, int N, int K, int reluN)
{
    constexpr int SS    = 32768;   // per stage: A 16KB + B 16KB
    constexpr int OFF_B = 16384;

    if (GRAMSYM && blockIdx.x < blockIdx.y) return;   // strict lower tiles skipped

    extern __shared__ __align__(1024) char smem[];
    const uint32_t sb = smem_u32(smem);
    float* sbias = (float*)(smem + 4 * SS);

    A += (long)blockIdx.z * sA;
    B += (long)blockIdx.z * sB;
    C += (long)blockIdx.z * sC;
    const int bm = blockIdx.y * 128;
    const int bn = blockIdx.x * 128;

    const int t = threadIdx.x;
    const int lane = t & 31;
    const int wid = t >> 5;
    const int warp_m = (wid & 1) * 64;
    const int warp_n = (wid >> 1) * 32;

    if (HASBIAS && t < 128) {
        const float* bp = bias + (long)blockIdx.z * sBias;
        int n = bn + t;
        sbias[t] = (n < N) ? bp[n] : 0.f;
    }

    // ---- loader assignment: 1024 16B-chunks per matrix per tile, 4/thread ----
    uint32_t aOff[4], bOff[4];
    const float* gA[4];
    const float* gB[4];
    uint32_t bSz[4];
#pragma unroll
    for (int i = 0; i < 4; i++) {
        int id = t + 256 * i;
        int row = id >> 3, ch = id & 7;
        aOff[i] = swz((uint32_t)row, (uint32_t)ch);
        bOff[i] = aOff[i];
        gA[i] = A + (long)(bm + row) * lda + ch * 4;
        gB[i] = B + (long)(bn + row) * ldb + ch * 4;
        bSz[i] = ((bn + row) < N) ? 16u : 0u;
    }

#define MG_LOAD(st, kt)                                                       \
    {                                                                         \
        const uint32_t s0 = sb + (uint32_t)(st) * SS;                         \
        _Pragma("unroll")                                                     \
        for (int i = 0; i < 4; i++) {                                         \
            CP16(s0 + aOff[i], gA[i] + (kt) * 32, 16u);                       \
            CP16(s0 + OFF_B + bOff[i], gB[i] + (kt) * 32, bSz[i]);            \
        }                                                                     \
    }

    // ---- fragment addressing ----
    const uint32_t rA  = (uint32_t)(warp_m + (lane & 7) + ((lane >> 3) & 1) * 8);
    const uint32_t cbA = (uint32_t)((lane >> 4) & 1);
    const uint32_t rB  = (uint32_t)(warp_n + (lane & 7) + ((lane >> 4) & 1) * 8);
    const uint32_t cbB = (uint32_t)((lane >> 3) & 1);
    const uint32_t xA = (uint32_t)(lane & 7);

    float acc[4][4][4];
#pragma unroll
    for (int i = 0; i < 4; i++)
#pragma unroll
        for (int j = 0; j < 4; j++)
#pragma unroll
            for (int q = 0; q < 4; q++) acc[i][j][q] = 0.f;

#define MG_MMA(st)                                                            \
    {                                                                         \
        const uint32_t s0 = sb + (uint32_t)(st) * SS;                         \
        _Pragma("unroll")                                                     \
        for (int s = 0; s < 4; s++) {                                         \
            const uint32_t coA = (((2u * s + cbA) ^ xA) & 7u) << 4;           \
            const uint32_t coB = (((2u * s + cbB) ^ xA) & 7u) << 4;           \
            uint32_t ar[4][4], br[4][2];                                      \
            _Pragma("unroll")                                                 \
            for (int i = 0; i < 4; i++)                                       \
                ldsm4(ar[i][0], ar[i][1], ar[i][2], ar[i][3],                 \
                      s0 + (rA + 16u * i) * 128u + coA);                      \
            _Pragma("unroll")                                                 \
            for (int p = 0; p < 2; p++)                                       \
                ldsm4(br[2*p][0], br[2*p][1], br[2*p+1][0], br[2*p+1][1],     \
                      s0 + OFF_B + (rB + 16u * p) * 128u + coB);              \
            if (TERMS == 3) {                                                 \
                uint32_t bh[4][2], bl[4][2];                                  \
                _Pragma("unroll")                                             \
                for (int j = 0; j < 4; j++)                                   \
                    _Pragma("unroll")                                         \
                    for (int q = 0; q < 2; q++) {                             \
                        float f = __uint_as_float(br[j][q]);                  \
                        uint32_t h = cvt_tf32(f);                             \
                        bh[j][q] = h;                                         \
                        bl[j][q] = __float_as_uint(f - __uint_as_float(h));   \
                    }                                                         \
                _Pragma("unroll")                                             \
                for (int i = 0; i < 4; i++) {                                 \
                    uint32_t ah[4], al[4];                                    \
                    _Pragma("unroll")                                         \
                    for (int q = 0; q < 4; q++) {                             \
                        float f = __uint_as_float(ar[i][q]);                  \
                        uint32_t h = cvt_tf32(f);                             \
                        ah[q] = h;                                            \
                        al[q] = __float_as_uint(f - __uint_as_float(h));      \
                    }                                                         \
                    _Pragma("unroll")                                         \
                    for (int j = 0; j < 4; j++) {                             \
                        mma8(acc[i][j], ah[0], ah[1], ah[2], ah[3],           \
                             bh[j][0], bh[j][1]);                             \
                        mma8(acc[i][j], ah[0], ah[1], ah[2], ah[3],           \
                             bl[j][0], bl[j][1]);                             \
                        mma8(acc[i][j], al[0], al[1], al[2], al[3],           \
                             bh[j][0], bh[j][1]);                             \
                    }                                                         \
                }                                                             \
            } else {                                                          \
                _Pragma("unroll")                                             \
                for (int j = 0; j < 4; j++)                                   \
                    _Pragma("unroll")                                         \
                    for (int q = 0; q < 2; q++)                               \
                        br[j][q] = cvt_tf32(__uint_as_float(br[j][q]));       \
                _Pragma("unroll")                                             \
                for (int i = 0; i < 4; i++) {                                 \
                    uint32_t ah[4];                                           \
                    _Pragma("unroll")                                         \
                    for (int q = 0; q < 4; q++)                               \
                        ah[q] = cvt_tf32(__uint_as_float(ar[i][q]));          \
                    _Pragma("unroll")                                         \
                    for (int j = 0; j < 4; j++)                               \
                        mma8(acc[i][j], ah[0], ah[1], ah[2], ah[3],           \
                             br[j][0], br[j][1]);                             \
                }                                                             \
            }                                                                 \
        }                                                                     \
    }

    // ---- 4-stage cp.async pipeline ----
    const int nkt = K >> 5;
#pragma unroll
    for (int p = 0; p < 3; p++) {
        if (p < nkt) MG_LOAD(p, p);
        CPCOMMIT();
    }
    for (int kt = 0; kt < nkt; kt++) {
        CPWAIT2();
        __syncthreads();
        MG_MMA(kt & 3);
        const int nx = kt + 3;
        if (nx < nkt) MG_LOAD(nx & 3, nx);
        CPCOMMIT();
    }

    // ---- epilogue: normal (m,n) write ----
    const bool ldcEven = ((ldc & 1) == 0);
    const int mrow = bm + warp_m + (lane >> 2);
#pragma unroll
    for (int i = 0; i < 4; i++) {
        const int m0 = mrow + i * 16;
        float* C0 = C + (long)m0 * ldc;
        float* C8 = C0 + (long)8 * ldc;
#pragma unroll
        for (int j = 0; j < 4; j++) {
            const int nb = warp_n + j * 8 + (lane & 3) * 2;  // even
            const int nn = bn + nb;
            if (nn >= N) continue;
            float v0 = acc[i][j][0], v1 = acc[i][j][1];
            float v2 = acc[i][j][2], v3 = acc[i][j][3];
            if (HASBIAS) {
                float b0 = sbias[nb], b1 = sbias[nb + 1];
                v0 += b0; v1 += b1; v2 += b0; v3 += b1;
            }
            if (RELU && nn < reluN) {
                v0 = fmaxf(v0, 0.f); v1 = fmaxf(v1, 0.f);
                v2 = fmaxf(v2, 0.f); v3 = fmaxf(v3, 0.f);
            }
            if (ldcEven) {
                *(float2*)(C0 + nn) = make_float2(v0, v1);
                *(float2*)(C8 + nn) = make_float2(v2, v3);
            } else {
                C0[nn] = v0; C0[nn + 1] = v1;
                C8[nn] = v2; C8[nn + 1] = v3;
            }
        }
    }

    // ---- mirror write for symmetric gram (off-diagonal tiles) ----
    if (GRAMSYM) {
        if (bm != bn) {
            __syncthreads();                     // all smem pipeline reads done
            float* tsm = (float*)smem;           // [128][132] transposed tile
#pragma unroll
            for (int i = 0; i < 4; i++) {
                const int ml = warp_m + (lane >> 2) + i * 16;
#pragma unroll
                for (int j = 0; j < 4; j++) {
                    const int nl = warp_n + j * 8 + (lane & 3) * 2;
                    tsm[nl * 132 + ml]           = acc[i][j][0];
                    tsm[(nl + 1) * 132 + ml]     = acc[i][j][1];
                    tsm[nl * 132 + ml + 8]       = acc[i][j][2];
                    tsm[(nl + 1) * 132 + ml + 8] = acc[i][j][3];
                }
            }
            __syncthreads();
            const int r = t >> 1;
            const int c0 = (t & 1) * 64;
            float* dst = C + (long)(bn + r) * ldc + bm + c0;
            const float* srow = tsm + r * 132 + c0;
#pragma unroll
            for (int q = 0; q < 64; q += 4)
                *(float4*)(dst + q) = *(const float4*)(srow + q);
        }
    }
#undef MG_LOAD
#undef MG_MMA
}

// ---------------- im2col for backbone grouped conv (groups=4, k=3, pad=1) ----
__global__ void im2col_k3(const float* __restrict__ h, float* __restrict__ xcol)
{
    size_t o = (size_t)blockIdx.x * blockDim.x + threadIdx.x;
    if (o >= (size_t)BTN * FEAT) return;
    int j = (int)(o % FEAT);
    size_t bt = o / FEAT;
    int t = (int)(bt & 1023);
    size_t b = bt >> 10;
    int g = j / 192, r = j % 192, i = r / 3, dt = r % 3;
    int ts = t + dt - 1;
    float v = 0.f;
    if (ts >= 0 && ts < TT) v = h[((b << 10) + ts) * HH + g * 64 + i];
    xcol[o] = v;
}

// ---------------- pack fused B = [t1w; s1w_nbr; s1w_ctr], bias = [t1b;0;s1b] --
__global__ void pack_fused(const float* __restrict__ t1w, const float* __restrict__ t1b,
                           const float* __restrict__ s1w, const float* __restrict__ s1b,
                           float* __restrict__ Bf, float* __restrict__ bf)
{
    int i = blockIdx.x * 256 + threadIdx.x;
    if (i < 384 * 256) {
        int r = i >> 8, c = i & 255;
        float v;
        if (r < 128)      v = t1w[r * 256 + c];
        else if (r < 256) v = s1w[(r - 128) * 512 + c];
        else              v = s1w[(r - 256) * 512 + 256 + c];
        Bf[i] = v;
    }
    if (i < 384)
        bf[i] = (i < 128) ? t1b[i] : (i < 256 ? 0.f : s1b[i - 256]);
}

// ---------------- t2: grouped conv1d (groups=32, 4 in/group, k=3, pad=1), relu
__global__ void t2conv(const float* __restrict__ x, int ldx,
                       const float* __restrict__ w,
                       const float* __restrict__ bias, float* __restrict__ y)
{
    __shared__ float sh[34][WW];
    const int b  = blockIdx.y;
    const int t0 = blockIdx.x * 32;
    const int o  = threadIdx.x;

#pragma unroll 2
    for (int r = 0; r < 34; r++) {
        int ts = t0 - 1 + r;
        sh[r][o] = (ts >= 0 && ts < TT) ? x[(((size_t)b << 10) + ts) * ldx + o] : 0.f;
    }
    __syncthreads();

    float wr[12];
#pragma unroll
    for (int q = 0; q < 12; q++) wr[q] = w[o * 12 + q];
    const float bb = bias[o];
    const int g4 = (o >> 2) << 2;

    for (int tt = 0; tt < 32; tt++) {
        float acc = bb;
#pragma unroll
        for (int i = 0; i < 4; i++)
#pragma unroll
            for (int dt = 0; dt < 3; dt++)
                acc = fmaf(wr[i * 3 + dt], sh[tt + dt][g4 + i], acc);
        y[(((size_t)b << 10) + t0 + tt) * WW + o] = fmaxf(acc, 0.f);
    }
}

// ---------------- per-frame squared L2 norms ----------------
__global__ void rownorm(const float* __restrict__ X, float* __restrict__ xx)
{
    int row = blockIdx.x * 8 + (threadIdx.x >> 5);
    int lane = threadIdx.x & 31;
    const float* p = X + (size_t)row * HH;
    float s = 0.f;
#pragma unroll
    for (int c = lane; c < HH; c += 32) { float v = p[c]; s = fmaf(v, v, s); }
#pragma unroll
    for (int off = 16; off; off >>= 1) s += __shfl_down_sync(0xffffffffu, s, off);
    if (!lane) xx[row] = s;
}

// ---------------- top-3 of (2*G[t,s] - xx[s]) per row; ties -> lower index ----
#define T3_INS(V, I)                                                            \
    do {                                                                        \
        float _v = (V); int _i = (I);                                           \
        if (_v > v0 || (_v == v0 && _i < i0)) {                                 \
            v2 = v1; i2 = i1; v1 = v0; i1 = i0; v0 = _v; i0 = _i;               \
        } else if (_v > v1 || (_v == v1 && _i < i1)) {                          \
            v2 = v1; i2 = i1; v1 = _v; i1 = _i;                                 \
        } else if (_v > v2 || (_v == v2 && _i < i2)) {                          \
            v2 = _v; i2 = _i;                                                   \
        }                                                                       \
    } while (0)

__global__ void top3_kernel(const float* __restrict__ gram,
                            const float* __restrict__ xx, int* __restrict__ idx)
{
    int gw = (blockIdx.x * blockDim.x + threadIdx.x) >> 5;
    if (gw >= BTN) return;
    int lane = threadIdx.x & 31;
    int b = gw >> 10, t = gw & 1023;
    const float* grow = gram + ((size_t)b * TT + t) * TT;
    const float* xr = xx + (b << 10);

    float v0 = -3e38f, v1 = -3e38f, v2 = -3e38f;
    int i0 = 1 << 29, i1 = 1 << 29, i2 = 1 << 29;
    for (int s = lane; s < TT; s += 32) {
        float v = fmaf(2.f, grow[s], -xr[s]);
        T3_INS(v, s);
    }
#pragma unroll
    for (int off = 16; off; off >>= 1) {
        float w0 = __shfl_down_sync(0xffffffffu, v0, off);
        float w1 = __shfl_down_sync(0xffffffffu, v1, off);
        float w2 = __shfl_down_sync(0xffffffffu, v2, off);
        int   j0 = __shfl_down_sync(0xffffffffu, i0, off);
        int   j1 = __shfl_down_sync(0xffffffffu, i1, off);
        int   j2 = __shfl_down_sync(0xffffffffu, i2, off);
        T3_INS(w0, j0); T3_INS(w1, j1); T3_INS(w2, j2);
    }
    if (!lane) { idx[gw * 3 + 0] = i0; idx[gw * 3 + 1] = i1; idx[gw * 3 + 2] = i2; }
}

// ---------------- fused s1-epilogue (gather + relu) + grouped s2 (4->4) ------
__global__ void s1s2(const float* __restrict__ Pn, const float* __restrict__ Pc, int ld,
                     const int* __restrict__ idx, const float* __restrict__ s2w,
                     const float* __restrict__ s2b, float* __restrict__ out)
{
    const int bt = blockIdx.x;
    const int c  = threadIdx.x;
    const int b  = bt >> 10;
    __shared__ float sh[3][WW];
    __shared__ int sidx[3];
    if (c < 3) sidx[c] = idx[bt * 3 + c];
    __syncthreads();

    const float pc = Pc[(size_t)bt * ld + c];
#pragma unroll
    for (int k = 0; k < 3; k++) {
        size_t j = ((size_t)(b << 10) + sidx[k]);
        sh[k][c] = fmaxf(Pn[j * ld + c] + pc, 0.f);
    }
    __syncthreads();

    const float w0 = s2w[c * 4 + 0], w1 = s2w[c * 4 + 1];
    const float w2 = s2w[c * 4 + 2], w3 = s2w[c * 4 + 3];
    const float bb = s2b[c];
    const int gb = (c >> 2) << 2;
#pragma unroll
    for (int k = 0; k < 3; k++) {
        float acc = bb;
        acc = fmaf(w0, sh[k][gb + 0], acc);
        acc = fmaf(w1, sh[k][gb + 1], acc);
        acc = fmaf(w2, sh[k][gb + 2], acc);
        acc = fmaf(w3, sh[k][gb + 3], acc);
        out[((size_t)bt * 3 + k) * WW + c] = fmaxf(acc, 0.f);
    }
}

// ---------------- combine: Y = relu(t3 + X + max_k s3 + s3b) -----------------
__global__ void combine(const float* __restrict__ t3, const float* __restrict__ X,
                        const float* __restrict__ s3, const float* __restrict__ s3b,
                        float* __restrict__ Y)
{
    size_t o = (size_t)blockIdx.x * HH + threadIdx.x;
    int c = threadIdx.x;
    size_t bt = blockIdx.x;
    const float* sp = s3 + bt * 3 * HH + c;
    float m = fmaxf(fmaxf(sp[0], sp[HH]), sp[2 * HH]);
    float v = t3[o] + X[o] + m + s3b[c];
    Y[o] = fmaxf(v, 0.f);
}

// ---------------- host side ----------------
static const int SHM = 4 * 32768 + 512;   // 4 stages + bias

template<int TERMS, bool RELU, bool HASBIAS, bool GRAMSYM>
static void launch_mgemm(dim3 grid,
                         const float* A, long sA, int lda,
                         const float* B, long sB, int ldb,
                         const float* bias, int sBias,
                         float* C, long sC, int ldc,
                         int M, int N, int K, int reluN)
{
    static bool init = [] {
        cudaFuncSetAttribute(mgemm<TERMS, RELU, HASBIAS, GRAMSYM>,
                             cudaFuncAttributeMaxDynamicSharedMemorySize, SHM);
        return true;
    }();
    (void)init;
    mgemm<TERMS, RELU, HASBIAS, GRAMSYM><<<grid, 256, SHM>>>(
        A, sA, lda, B, sB, ldb, bias, sBias, C, sC, ldc, M, N, K, reluN);
}

static void tgemm(const float* A, long sA, int lda,
                  const float* B, long sB, int ldb,
                  const float* bias, int sBias,
                  float* C, long sC, int ldc,
                  int M, int N, int K, int batches, bool relu, int reluN,
                  int terms, bool gramsym = false)
{
    dim3 grid((N + 127) / 128, M / 128, batches);
    if (gramsym) {
        launch_mgemm<3, false, false, true>(grid, A, sA, lda, B, sB, ldb, nullptr, 0,
                                            C, sC, ldc, M, N, K, 0);
    } else if (terms == 3) {
        if (relu)
            launch_mgemm<3, true, true, false>(grid, A, sA, lda, B, sB, ldb, bias, sBias,
                                               C, sC, ldc, M, N, K, reluN);
        else if (bias)
            launch_mgemm<3, false, true, false>(grid, A, sA, lda, B, sB, ldb, bias, sBias,
                                                C, sC, ldc, M, N, K, 0);
        else
            launch_mgemm<3, false, false, false>(grid, A, sA, lda, B, sB, ldb, nullptr, 0,
                                                 C, sC, ldc, M, N, K, 0);
    } else {
        launch_mgemm<1, false, true, false>(grid, A, sA, lda, B, sB, ldb, bias, sBias,
                                            C, sC, ldc, M, N, K, 0);
    }
}

extern "C" void kernel_launch(void* const* d_in, const int* in_sizes, int n_in,
                              void* d_out, int out_size)
{
    const float* x      = (const float*)d_in[0];
    const float* fcin_w = (const float*)d_in[1];
    const float* fcin_b = (const float*)d_in[2];
    const float* conv_w = (const float*)d_in[3];
    const float* conv_b = (const float*)d_in[4];
    const float* t1w    = (const float*)d_in[5];
    const float* t1b    = (const float*)d_in[6];
    const float* t2w    = (const float*)d_in[7];
    const float* t2b    = (const float*)d_in[8];
    const float* t3w    = (const float*)d_in[9];
    const float* t3b    = (const float*)d_in[10];
    const float* s1w    = (const float*)d_in[11];
    const float* s1b    = (const float*)d_in[12];
    const float* s2w    = (const float*)d_in[13];
    const float* s2b    = (const float*)d_in[14];
    const float* s3w    = (const float*)d_in[15];
    const float* s3b    = (const float*)d_in[16];
    const float* fcw    = (const float*)d_in[17];
    const float* fcb    = (const float*)d_in[18];

    void *vp;
    float *p_h0, *p_h1, *p_big, *p_t2, *p_t3, *p_gram, *p_xx, *p_s2, *p_s3, *p_bf, *p_bfb;
    int *p_idx;
    cudaGetSymbolAddress(&vp, g_h0);   p_h0   = (float*)vp;
    cudaGetSymbolAddress(&vp, g_h1);   p_h1   = (float*)vp;
    cudaGetSymbolAddress(&vp, g_big);  p_big  = (float*)vp;
    cudaGetSymbolAddress(&vp, g_t2);   p_t2   = (float*)vp;
    cudaGetSymbolAddress(&vp, g_t3);   p_t3   = (float*)vp;
    cudaGetSymbolAddress(&vp, g_gram); p_gram = (float*)vp;
    cudaGetSymbolAddress(&vp, g_xx);   p_xx   = (float*)vp;
    cudaGetSymbolAddress(&vp, g_idx);  p_idx  = (int*)vp;
    cudaGetSymbolAddress(&vp, g_s2);   p_s2   = (float*)vp;
    cudaGetSymbolAddress(&vp, g_s3);   p_s3   = (float*)vp;
    cudaGetSymbolAddress(&vp, g_bf);   p_bf   = (float*)vp;
    cudaGetSymbolAddress(&vp, g_bfb);  p_bfb  = (float*)vp;

    // 1) fc_in + relu : [BTN,768] x [256,768]^T -> g_h0
    tgemm(x, 0, FEAT, fcin_w, 0, FEAT, fcin_b, 0, p_h0, 0, HH, BTN, HH, FEAT, 1, true, HH, 3);

    // 2) backbone grouped conv via im2col + 4 batched GEMMs (relu) -> g_h1
    {
        size_t tot = (size_t)BTN * FEAT;
        im2col_k3<<<(unsigned)((tot + 255) / 256), 256>>>(p_h0, p_big);
        tgemm(p_big, 192, FEAT, conv_w, 64 * 192, 192, conv_b, 64,
              p_h1, 64, HH, BTN, 64, 192, 4, true, 64, 3);
    }

    // 3) GCNeXt blocks
    for (int l = 0; l < LL; l++) {
        const float* X = (l == 0) ? p_h1 : p_h0;
        float*       Y = (l == 0) ? p_h0 : p_h1;
        const float* t1wl = t1w + (size_t)l * WW * HH;
        const float* t3wl = t3w + (size_t)l * HH * WW;
        const float* s1wl = s1w + (size_t)l * WW * (2 * HH);
        const float* s3wl = s3w + (size_t)l * HH * WW;

        // fused t1|Pn|Pc GEMM: N=384, relu only on first 128 cols (t1)
        pack_fused<<<384, 256>>>(t1wl, t1b + (size_t)l * WW, s1wl, s1b + (size_t)l * WW,
                                 p_bf, p_bfb);
        tgemm(X, 0, HH, p_bf, 0, HH, p_bfb, 0, p_big, 0, 384, BTN, 384, HH, 1, true, 128, 3);

        // temporal branch rest
        t2conv<<<dim3(TT / 32, BB), WW>>>(p_big, 384, t2w + (size_t)l * WW * 12,
                                          t2b + (size_t)l * WW, p_t2);
        tgemm(p_t2, 0, WW, t3wl, 0, WW, t3b + (size_t)l * HH, 0, p_t3, 0, HH, BTN, HH, WW, 1, false, 0, 3);

        // kNN graph: symmetric gram (upper tiles + mirror)
        rownorm<<<BTN / 8, 256>>>(X, p_xx);
        tgemm(X, (long)TT * HH, HH, X, (long)TT * HH, HH, nullptr, 0,
              p_gram, (long)TT * TT, TT, TT, TT, HH, BB, false, 0, 3, true);
        top3_kernel<<<(BTN * 32 + 255) / 256, 256>>>(p_gram, p_xx, p_idx);

        // semantic branch: gather from fused Pn/Pc columns
        s1s2<<<BTN, WW>>>(p_big + 128, p_big + 256, 384, p_idx,
                          s2w + (size_t)l * WW * 4, s2b + (size_t)l * WW, p_s2);

        // s3 GEMM over BTN*3 rows, then max_k + residual + relu
        tgemm(p_s2, 0, WW, s3wl, 0, WW, nullptr, 0, p_s3, 0, HH, BTN * 3, HH, WW, 1, false, 0, 3);
        combine<<<BTN, HH>>>(p_t3, X, p_s3, s3b + (size_t)l * HH, Y);
    }

    // 4) final fc: [BTN,256] x [50,256]^T + b -> d_out (single-pass tf32)
    tgemm(p_h1, 0, HH, fcw, 0, HH, fcb, 0, (float*)d_out, 0, CC, BTN, CC, HH, 1, false, 0, 1);
}